// round 13
// baseline (speedup 1.0000x reference)
#include <cuda_runtime.h>
#include <cuda_fp16.h>
#include <math.h>
#include <stdint.h>

#define XLEN 2048
#define YLEN 1024
#define BSZ  8
#define XD   1024
#define YD   1024
#define HD   512
#define YOUT 1024
#define CATD (YD + HD)
#define FMAXV 3.402823466e38f
#define H16MAX 65504.0f
#define INV_SQRT_HD 0.04419417382415922f

// ===================== PTX helpers =====================
__device__ __forceinline__ uint32_t smem_u32(const void* p) {
    uint32_t a;
    asm("{ .reg .u64 t; cvta.to.shared.u64 t, %1; cvt.u32.u64 %0, t; }" : "=r"(a) : "l"(p));
    return a;
}
#define CP16(dst, src) \
    asm volatile("cp.async.cg.shared.global [%0], [%1], 16;" :: "r"(dst), "l"(src))
#define CP_COMMIT() asm volatile("cp.async.commit_group;")
#define PREF_L2(p) asm volatile("prefetch.global.L2 [%0];" :: "l"(p))

#define LDSM4(r, a) \
    asm volatile("ldmatrix.sync.aligned.m8n8.x4.shared.b16 {%0,%1,%2,%3}, [%4];" \
        : "=r"((r)[0]), "=r"((r)[1]), "=r"((r)[2]), "=r"((r)[3]) : "r"(a))

#define MMA_F16(d, a, b0v, b1v) \
    asm volatile("mma.sync.aligned.m16n8k16.row.col.f32.f16.f16.f32 " \
        "{%0,%1,%2,%3}, {%4,%5,%6,%7}, {%8,%9}, {%0,%1,%2,%3};" \
        : "+f"((d)[0]), "+f"((d)[1]), "+f"((d)[2]), "+f"((d)[3]) \
        : "r"((a)[0]), "r"((a)[1]), "r"((a)[2]), "r"((a)[3]), "r"(b0v), "r"(b1v))

// SMEM tile: 128 rows x 64 f16 (128B/row, 8 x 16B chunks), conflict-free swizzle.
__device__ __forceinline__ uint32_t swz64(int row, int ch) {
    return (uint32_t)(row * 128 + ((ch ^ (row & 7)) << 4));
}

// ===================== scratch (device globals) ==========================
#define AL __align__(16)
__device__ AL __half g_Xhi[XLEN * BSZ * XD];
__device__ AL __half g_Yhi[YLEN * BSZ * YD];
__device__ AL __half g_Xkw_hi[HD * XD];
__device__ AL __half g_Xvw_hi[HD * XD];
__device__ AL __half g_Yqw_hi[HD * YD];
__device__ AL __half g_Yww_hi[YOUT * CATD];
__device__ AL __half g_xk_hi[XLEN * BSZ * HD];
__device__ AL __half g_yq_hi[YLEN * BSZ * HD];
__device__ AL __half g_xvT_hi[BSZ * HD * XLEN];
__device__ AL __half g_af_hi[YLEN * BSZ * HD];
__device__ AL float  g_biasf[BSZ * YLEN * XLEN];      // sig*align + mask fill
__device__ AL __half g_lattn[BSZ * YLEN * XLEN];      // logits -> attn in place

// ===================== fused split: fp32 -> fp16 hi ======================
struct SplitArgs {
    const float* src[6];
    __half* hi[6];
    long n4[6];
};

__global__ __launch_bounds__(256) void split_all(SplitArgs s)
{
    const int e = blockIdx.y;
    long i4 = (long)blockIdx.x * 256 + threadIdx.x;
    if (i4 >= s.n4[e]) return;
    long base = i4 * 4;
    float4 v = *(const float4*)(s.src[e] + base);
    __half2 hp0 = {__float2half_rn(v.x), __float2half_rn(v.y)};
    __half2 hp1 = {__float2half_rn(v.z), __float2half_rn(v.w)};
    *(uint2*)(s.hi[e] + base) = make_uint2(*(uint32_t*)&hp0, *(uint32_t*)&hp1);
}

// ===================== softmax: fp16 logits -> fp16 attn (in place) ======
__global__ __launch_bounds__(256) void softmax_kernel()
{
    const long row = blockIdx.x;
    __half2* p = (__half2*)(g_lattn + row * XLEN);   // 1024 half2
    const int tid = threadIdx.x;

    float v[8];
#pragma unroll
    for (int i = 0; i < 4; i++) {
        float2 t = __half22float2(p[tid + (i << 8)]);
        v[i * 2] = t.x; v[i * 2 + 1] = t.y;
    }
    float mx = -FMAXV;
#pragma unroll
    for (int i = 0; i < 8; i++) mx = fmaxf(mx, v[i]);

    __shared__ float sred[8];
#pragma unroll
    for (int o = 16; o > 0; o >>= 1) mx = fmaxf(mx, __shfl_xor_sync(0xffffffff, mx, o));
    if ((tid & 31) == 0) sred[tid >> 5] = mx;
    __syncthreads();
    mx = sred[0];
#pragma unroll
    for (int w = 1; w < 8; w++) mx = fmaxf(mx, sred[w]);
    __syncthreads();

    float s = 0.0f;
#pragma unroll
    for (int i = 0; i < 8; i++) { v[i] = expf(v[i] - mx); s += v[i]; }
#pragma unroll
    for (int o = 16; o > 0; o >>= 1) s += __shfl_xor_sync(0xffffffff, s, o);
    if ((tid & 31) == 0) sred[tid >> 5] = s;
    __syncthreads();
    s = 0.0f;
#pragma unroll
    for (int w = 0; w < 8; w++) s += sred[w];

    const float inv = 1.0f / s;
#pragma unroll
    for (int i = 0; i < 4; i++) {
        __half2 h = {__float2half_rn(v[i * 2] * inv), __float2half_rn(v[i * 2 + 1] * inv)};
        p[tid + (i << 8)] = h;
    }
}

// ===================== fp16 GEMM core ====================================
// MODE 0: fp16 out (+bias col/row, scale).
// MODE 1: logits: v + biasf, clamp, -> fp16 (into g.Chi).
// MODE 2: +bias -> fp32.  MODE 3: accumulate into fp32 C.
struct GemmArgs {
    const __half *Ah, *Bh;
    long lda, ldb, Abatch, Bbatch;
    int K;
    float* Cf;
    __half *Chi;
    long ldc, Cbatch;
    const float* bias;
    int bias_rows;
    float scale;
    const float* biasf;     // MODE 1: precombined fp32 bias
};

#define STG   32768            // Ah 16K | Bh 16K
#define NSTG  3
#define EPIT  136
#define SMEM_BYTES (NSTG * STG)

template <int MODE>
__device__ __forceinline__ void gemm_body(const GemmArgs& g, int bx, int by, int b)
{
    extern __shared__ char smem[];
    const uint32_t sb = smem_u32(smem);
    const int tid = threadIdx.x, wid = tid >> 5, lane = tid & 31;
    const long m0 = (long)by * 128, n0 = (long)bx * 128;
    const int wm = (wid >> 2) * 64;
    const int wn = (wid & 3) * 32;

    const __half* Ah = g.Ah + (long)b * g.Abatch;
    const __half* Bh = g.Bh + (long)b * g.Bbatch;

    const int lrow = tid >> 3, lch = tid & 7;
    const uint32_t sw0 = swz64(lrow, lch);
    const long ga0 = (m0 + lrow) * g.lda + lch * 8;
    const long gb0 = (n0 + lrow) * g.ldb + lch * 8;
    const long astep = 32 * g.lda, bstep = 32 * g.ldb;

    const int NT = g.K >> 6;
    const int a_r = lane & 15, a_c = lane >> 4;
    const int b_r = (lane & 7) + ((lane >> 4) & 1) * 8, b_c = (lane >> 3) & 1;

    float acc[4][4][4];
#pragma unroll
    for (int i = 0; i < 4; i++)
#pragma unroll
        for (int j = 0; j < 4; j++)
#pragma unroll
            for (int k = 0; k < 4; k++) acc[i][j][k] = 0.0f;

    auto load_stage = [&](int s, int it) {
        const long k0 = (long)it << 6;
        const uint32_t base = sb + s * STG;
#pragma unroll
        for (int i = 0; i < 4; i++) {
            CP16(base + sw0 + i * 4096,         (const char*)(Ah + ga0 + i * astep + k0));
            CP16(base + 16384 + sw0 + i * 4096, (const char*)(Bh + gb0 + i * bstep + k0));
        }
        CP_COMMIT();
    };

    load_stage(0, 0);
    load_stage(1, 1);

    // warm L2 with the epilogue's gmem inputs while the mainloop runs
    if (MODE == 1) {
#pragma unroll
        for (int i = 0; i < 2; i++) {
            const int gid = tid + i * 256;           // 512 ids: 128 rows x 4 segs
            const int row = gid >> 2, seg = gid & 3;
            const long idx = (long)b * g.Cbatch + (m0 + row) * g.ldc + n0 + seg * 32;
            PREF_L2(g.biasf + idx);
        }
    } else if (MODE == 3) {
#pragma unroll
        for (int i = 0; i < 2; i++) {
            const int gid = tid + i * 256;
            const int row = gid >> 2, seg = gid & 3;
            const long idx = (long)b * g.Cbatch + (m0 + row) * g.ldc + n0 + seg * 32;
            PREF_L2(g.Cf + idx);
        }
    }

    int cur = 0, nxt = 2;
    for (int it = 0; it < NT; ++it) {
        asm volatile("cp.async.wait_group 1;");
        __syncthreads();
        if (it + 2 < NT) {
            load_stage(nxt, it + 2);
            if (++nxt == NSTG) nxt = 0;
        } else CP_COMMIT();

        const uint32_t st = sb + cur * STG;
        if (++cur == NSTG) cur = 0;
#pragma unroll
        for (int ks = 0; ks < 4; ks++) {
            const int kc = ks * 2;
            uint32_t ah[4][4], bh[2][4];
#pragma unroll
            for (int mi = 0; mi < 4; mi++)
                LDSM4(ah[mi], st + swz64(wm + mi * 16 + a_r, kc + a_c));
#pragma unroll
            for (int nb = 0; nb < 2; nb++)
                LDSM4(bh[nb], st + 16384 + swz64(wn + nb * 16 + b_r, kc + b_c));
#pragma unroll
            for (int mi = 0; mi < 4; mi++)
#pragma unroll
                for (int ni = 0; ni < 4; ni++) {
                    const int nb = ni >> 1, sub = (ni & 1) * 2;
                    MMA_F16(acc[mi][ni], ah[mi], bh[nb][sub], bh[nb][sub + 1]);
                }
        }
    }
    __syncthreads();   // pipeline smem now reusable as staging

    // ---- stage acc tile to smem ----
    float* sf = (float*)smem;
#pragma unroll
    for (int mi = 0; mi < 4; mi++)
#pragma unroll
        for (int ni = 0; ni < 4; ni++) {
            const int row = wm + mi * 16 + (lane >> 2);
            const int col = wn + ni * 8 + (lane & 3) * 2;
            *(float2*)&sf[row * EPIT + col] =
                make_float2(acc[mi][ni][0], acc[mi][ni][1]);
            *(float2*)&sf[(row + 8) * EPIT + col] =
                make_float2(acc[mi][ni][2], acc[mi][ni][3]);
        }
    __syncthreads();

    // ---- thread-linear gmem phase: coalesced 16B transactions ----
    if (MODE == 0) {
        const float sc = g.scale;
#pragma unroll
        for (int i = 0; i < 8; i++) {
            const int gid = tid + i * 256;
            const int row = gid >> 4, c0 = (gid & 15) * 8;
            float4 va = *(float4*)&sf[row * EPIT + c0];
            float4 vb = *(float4*)&sf[row * EPIT + c0 + 4];
            float v[8] = {va.x, va.y, va.z, va.w, vb.x, vb.y, vb.z, vb.w};
            if (g.bias) {
                if (g.bias_rows) {
                    const float br = __ldg(&g.bias[m0 + row]);
#pragma unroll
                    for (int j = 0; j < 8; j++) v[j] += br;
                } else {
                    float4 b0 = *(const float4*)&g.bias[n0 + c0];
                    float4 b1 = *(const float4*)&g.bias[n0 + c0 + 4];
                    v[0] += b0.x; v[1] += b0.y; v[2] += b0.z; v[3] += b0.w;
                    v[4] += b1.x; v[5] += b1.y; v[6] += b1.z; v[7] += b1.w;
                }
            }
            uint4 u;
            __half2 h0 = {__float2half_rn(v[0] * sc), __float2half_rn(v[1] * sc)};
            __half2 h1 = {__float2half_rn(v[2] * sc), __float2half_rn(v[3] * sc)};
            __half2 h2 = {__float2half_rn(v[4] * sc), __float2half_rn(v[5] * sc)};
            __half2 h3 = {__float2half_rn(v[6] * sc), __float2half_rn(v[7] * sc)};
            u.x = *(uint32_t*)&h0; u.y = *(uint32_t*)&h1;
            u.z = *(uint32_t*)&h2; u.w = *(uint32_t*)&h3;
            const long idx = (long)b * g.Cbatch + (m0 + row) * g.ldc + n0 + c0;
            *(uint4*)(g.Chi + idx) = u;
        }
    } else if (MODE == 1) {
#pragma unroll
        for (int i = 0; i < 8; i++) {
            const int gid = tid + i * 256;
            const int row = gid >> 4, c0 = (gid & 15) * 8;
            float4 va = *(float4*)&sf[row * EPIT + c0];
            float4 vb = *(float4*)&sf[row * EPIT + c0 + 4];
            float v[8] = {va.x, va.y, va.z, va.w, vb.x, vb.y, vb.z, vb.w};
            const long idx = (long)b * g.Cbatch + (m0 + row) * g.ldc + n0 + c0;
            float4 b0 = *(const float4*)(g.biasf + idx);
            float4 b1 = *(const float4*)(g.biasf + idx + 4);
            float bb[8] = {b0.x, b0.y, b0.z, b0.w, b1.x, b1.y, b1.z, b1.w};
            uint4 u;
            __half2 hh[4];
#pragma unroll
            for (int j = 0; j < 8; j++) {
                float o = v[j] + bb[j];
                o = fminf(fmaxf(o, -H16MAX), H16MAX);
                if ((j & 1) == 0) hh[j >> 1].x = __float2half_rn(o);
                else              hh[j >> 1].y = __float2half_rn(o);
            }
            u.x = *(uint32_t*)&hh[0]; u.y = *(uint32_t*)&hh[1];
            u.z = *(uint32_t*)&hh[2]; u.w = *(uint32_t*)&hh[3];
            *(uint4*)(g.Chi + idx) = u;
        }
    } else if (MODE == 2) {
#pragma unroll
        for (int i = 0; i < 16; i++) {
            const int gid = tid + i * 256;
            const int row = gid >> 5, c0 = (gid & 31) * 4;
            float4 v = *(float4*)&sf[row * EPIT + c0];
            float4 b4 = *(const float4*)&g.bias[n0 + c0];
            const long idx = (long)b * g.Cbatch + (m0 + row) * g.ldc + n0 + c0;
            *(float4*)(g.Cf + idx) =
                make_float4(v.x + b4.x, v.y + b4.y, v.z + b4.z, v.w + b4.w);
        }
    } else {  // MODE 3: accumulate
#pragma unroll
        for (int i = 0; i < 16; i++) {
            const int gid = tid + i * 256;
            const int row = gid >> 5, c0 = (gid & 31) * 4;
            float4 v = *(float4*)&sf[row * EPIT + c0];
            const long idx = (long)b * g.Cbatch + (m0 + row) * g.ldc + n0 + c0;
            float4 o = *(float4*)(g.Cf + idx);
            *(float4*)(g.Cf + idx) =
                make_float4(v.x + o.x, v.y + o.y, v.z + o.z, v.w + o.w);
        }
    }
}

template <int MODE>
__global__ __launch_bounds__(256, 2) void mma_gemm(GemmArgs g)
{
    gemm_body<MODE>(g, blockIdx.x, blockIdx.y, blockIdx.z);
}

// proj launch: {xk, xk, yq, biascombine} striped per 4 ids (1024 blocks)
struct GemmP {
    GemmArgs a[2];
    const float* align;
    const int*   mask;
    const float* alignw;
    float* biasf;
};
__global__ __launch_bounds__(256, 2) void mma_gemm_proj(GemmP p)
{
    const int id = blockIdx.x;
    const int grp = id >> 2, r = id & 3;
    if (r < 2) {
        const int t = grp * 2 + r;     // 0..511 : xk  (4 nblk x 128 mblk)
        gemm_body<0>(p.a[0], t & 3, t >> 2, 0);
    } else if (r == 2) {
        const int t = grp;             // 0..255 : yq  (4 nblk x 64 mblk)
        gemm_body<0>(p.a[1], t & 3, t >> 2, 0);
    } else {
        // bias combine: biasf = sig*align + (mask ? -FMAX : 0)
        const float sig = 1.0f / (1.0f + expf(-__ldg(p.alignw)));
        const long base = (long)grp * 65536;           // 256 blocks x 64K floats
        const int tid = threadIdx.x;
#pragma unroll 4
        for (int i = 0; i < 64; i++) {
            const long idx = base + (long)i * 1024 + tid * 4;
            float4 av = *(const float4*)(p.align + idx);
            int4   mv = *(const int4*)(p.mask + idx);
            float4 o;
            o.x = sig * av.x + (mv.x ? -FMAXV : 0.0f);
            o.y = sig * av.y + (mv.y ? -FMAXV : 0.0f);
            o.z = sig * av.z + (mv.z ? -FMAXV : 0.0f);
            o.w = sig * av.w + (mv.w ? -FMAXV : 0.0f);
            *(float4*)(p.biasf + idx) = o;
        }
    }
}

// mega: logits(1024) | xvT(512) | out1(512), striped {lg,lg,xv,o1} per 4 ids
struct Gemm3 { GemmArgs lg, xv, o1; };
__global__ __launch_bounds__(256, 2) void mma_mega(Gemm3 p)
{
    const int id = blockIdx.x;
    const int grp = id >> 2, r = id & 3;
    if (r < 2) {
        const int t = grp * 2 + r;     // 0..1023 : logits (16 x 8 x 8)
        gemm_body<1>(p.lg, t & 15, (t >> 4) & 7, t >> 7);
    } else if (r == 2) {
        const int t = grp;             // 0..511 : xvT (16 x 4 x 8)
        gemm_body<0>(p.xv, t & 15, (t >> 4) & 3, t >> 6);
    } else {
        const int t = grp;             // 0..511 : out1 (8 x 64)
        gemm_body<2>(p.o1, t & 7, t >> 3, 0);
    }
}

// ===================== launch ============================================
extern "C" void kernel_launch(void* const* d_in, const int* in_sizes, int n_in,
                              void* d_out, int out_size)
{
    const float* X         = (const float*)d_in[0];
    const float* Y         = (const float*)d_in[1];
    const float* alignment = (const float*)d_in[2];
    const int*   mask      = (const int*)d_in[3];
    const float* Xk_w      = (const float*)d_in[4];
    const float* Xk_b      = (const float*)d_in[5];
    const float* Xv_w      = (const float*)d_in[6];
    const float* Xv_b      = (const float*)d_in[7];
    const float* Yq_w      = (const float*)d_in[8];
    const float* Yq_b      = (const float*)d_in[9];
    const float* Yw_w      = (const float*)d_in[10];
    const float* Yw_b      = (const float*)d_in[11];
    const float* align_w   = (const float*)d_in[12];
    float* out = (float*)d_out;

    cudaFuncSetAttribute((const void*)mma_gemm<0>, cudaFuncAttributeMaxDynamicSharedMemorySize, SMEM_BYTES);
    cudaFuncSetAttribute((const void*)mma_gemm<3>, cudaFuncAttributeMaxDynamicSharedMemorySize, SMEM_BYTES);
    cudaFuncSetAttribute((const void*)mma_gemm_proj, cudaFuncAttributeMaxDynamicSharedMemorySize, SMEM_BYTES);
    cudaFuncSetAttribute((const void*)mma_mega, cudaFuncAttributeMaxDynamicSharedMemorySize, SMEM_BYTES);

#define SYM(p, s) do { void* _t; cudaGetSymbolAddress(&_t, s); p = (decltype(p))_t; } while (0)
    __half *Xhi, *Yhi, *Xkw_hi, *Xvw_hi, *Yqw_hi, *Yww_hi,
        *xk_hi, *yq_hi, *xvT_hi, *af_hi, *lattn;
    float* biasf;
    SYM(Xhi, g_Xhi); SYM(Yhi, g_Yhi);
    SYM(Xkw_hi, g_Xkw_hi); SYM(Xvw_hi, g_Xvw_hi);
    SYM(Yqw_hi, g_Yqw_hi); SYM(Yww_hi, g_Yww_hi);
    SYM(xk_hi, g_xk_hi); SYM(yq_hi, g_yq_hi); SYM(xvT_hi, g_xvT_hi);
    SYM(af_hi, g_af_hi); SYM(lattn, g_lattn); SYM(biasf, g_biasf);

    // ---- fused split (1 launch, contiguous hi-only) ----
    SplitArgs sa;
    sa.src[0] = X;    sa.hi[0] = Xhi;    sa.n4[0] = (long)XLEN * BSZ * XD / 4;
    sa.src[1] = Y;    sa.hi[1] = Yhi;    sa.n4[1] = (long)YLEN * BSZ * YD / 4;
    sa.src[2] = Xk_w; sa.hi[2] = Xkw_hi; sa.n4[2] = (long)HD * XD / 4;
    sa.src[3] = Xv_w; sa.hi[3] = Xvw_hi; sa.n4[3] = (long)HD * XD / 4;
    sa.src[4] = Yq_w; sa.hi[4] = Yqw_hi; sa.n4[4] = (long)HD * YD / 4;
    sa.src[5] = Yw_w; sa.hi[5] = Yww_hi; sa.n4[5] = (long)YOUT * CATD / 4;
    long maxn4 = sa.n4[0];
    for (int i = 1; i < 6; i++) if (sa.n4[i] > maxn4) maxn4 = sa.n4[i];
    split_all<<<dim3((unsigned)((maxn4 + 255) / 256), 6), 256>>>(sa);

    // ---- proj launch: xk, yq GEMMs + bias combine (striped) ----
    GemmP pp = {};
    {
        GemmArgs a = {};
        a.Ah = Xhi; a.lda = XD; a.Abatch = 0;
        a.Bh = Xkw_hi; a.ldb = XD; a.Bbatch = 0;
        a.K = XD; a.Chi = xk_hi; a.ldc = HD; a.Cbatch = 0;
        a.bias = Xk_b; a.bias_rows = 0; a.scale = 1.0f;
        pp.a[0] = a;

        a.Ah = Yhi; a.lda = YD;
        a.Bh = Yqw_hi; a.ldb = YD;
        a.Chi = yq_hi; a.bias = Yq_b; a.scale = INV_SQRT_HD;
        pp.a[1] = a;

        pp.align = alignment; pp.mask = mask; pp.alignw = align_w; pp.biasf = biasf;
    }
    mma_gemm_proj<<<1024, 256, SMEM_BYTES>>>(pp);

    // ---- mega: logits + xvT + out1 (striped 2048-block launch) ----
    Gemm3 p3 = {};
    {
        GemmArgs a = {};
        // logits: per batch M=1024(y) N=2048(x) K=512 -> fp16 in-place buffer
        a.Ah = yq_hi; a.lda = BSZ * HD; a.Abatch = HD;
        a.Bh = xk_hi; a.ldb = BSZ * HD; a.Bbatch = HD;
        a.K = HD; a.Chi = lattn; a.ldc = XLEN; a.Cbatch = (long)YLEN * XLEN;
        a.biasf = biasf; a.scale = 1.0f;
        p3.lg = a;

        // xvT[b,h,x] = Xv_w @ X[.,b,.]^T + Xv_b(row) : M=512(h) N=2048(x) K=1024
        a = {};
        a.Ah = Xvw_hi; a.lda = XD; a.Abatch = 0;
        a.Bh = Xhi; a.ldb = (long)BSZ * XD; a.Bbatch = XD;
        a.K = XD; a.Chi = xvT_hi; a.ldc = XLEN; a.Cbatch = (long)HD * XLEN;
        a.bias = Xv_b; a.bias_rows = 1; a.scale = 1.0f;
        p3.xv = a;

        // out1 = Y @ Yw[:, :YD]^T + bias : M=8192 N=1024 K=1024
        a = {};
        a.Ah = Yhi; a.lda = YD; a.Abatch = 0;
        a.Bh = Yww_hi; a.ldb = CATD; a.Bbatch = 0;
        a.K = YD; a.Cf = out; a.ldc = YOUT; a.Cbatch = 0;
        a.bias = Yw_b; a.bias_rows = 0; a.scale = 1.0f;
        p3.o1 = a;
    }
    mma_mega<<<2048, 256, SMEM_BYTES>>>(p3);

    // ---- softmax (in place, fp16) ----
    softmax_kernel<<<BSZ * YLEN, 256>>>();

    GemmArgs a = {};

    // ---- attn_feat = attn @ xvT^T -> af[(y,b),h] : per batch ----
    a.Ah = lattn; a.lda = XLEN; a.Abatch = (long)YLEN * XLEN;
    a.Bh = xvT_hi; a.ldb = XLEN; a.Bbatch = (long)HD * XLEN;
    a.K = XLEN; a.Chi = af_hi;
    a.ldc = (long)BSZ * HD; a.Cbatch = HD;
    a.bias = nullptr; a.bias_rows = 0; a.scale = 1.0f;
    mma_gemm<0><<<dim3(HD / 128, YLEN / 128, BSZ), 256, SMEM_BYTES>>>(a);

    // ---- out += af @ Yw[:, YD:]^T : M=8192 N=1024 K=512 (accumulate) ----
    a = {};
    a.Ah = af_hi; a.lda = HD; a.Abatch = 0;
    a.Bh = Yww_hi + YD; a.ldb = CATD; a.Bbatch = 0;
    a.K = HD; a.Cf = out; a.ldc = YOUT; a.Cbatch = 0;
    a.bias = nullptr; a.bias_rows = 0; a.scale = 1.0f;
    mma_gemm<3><<<dim3(YOUT / 128, YLEN * BSZ / 128, 1), 256, SMEM_BYTES>>>(a);
}

// round 14
// speedup vs baseline: 1.0943x; 1.0943x over previous
#include <cuda_runtime.h>
#include <cuda_fp16.h>
#include <math.h>
#include <stdint.h>

#define XLEN 2048
#define YLEN 1024
#define BSZ  8
#define XD   1024
#define YD   1024
#define HD   512
#define YOUT 1024
#define CATD (YD + HD)
#define FMAXV 3.402823466e38f
#define H16MAX 65504.0f
#define INV_SQRT_HD 0.04419417382415922f

// ===================== PTX helpers =====================
__device__ __forceinline__ uint32_t smem_u32(const void* p) {
    uint32_t a;
    asm("{ .reg .u64 t; cvta.to.shared.u64 t, %1; cvt.u32.u64 %0, t; }" : "=r"(a) : "l"(p));
    return a;
}
#define CP16(dst, src) \
    asm volatile("cp.async.cg.shared.global [%0], [%1], 16;" :: "r"(dst), "l"(src))
#define CP_COMMIT() asm volatile("cp.async.commit_group;")
#define PREF_L2(p) asm volatile("prefetch.global.L2 [%0];" :: "l"(p))

#define LDSM4(r, a) \
    asm volatile("ldmatrix.sync.aligned.m8n8.x4.shared.b16 {%0,%1,%2,%3}, [%4];" \
        : "=r"((r)[0]), "=r"((r)[1]), "=r"((r)[2]), "=r"((r)[3]) : "r"(a))

#define MMA_F16(d, a, b0v, b1v) \
    asm volatile("mma.sync.aligned.m16n8k16.row.col.f32.f16.f16.f32 " \
        "{%0,%1,%2,%3}, {%4,%5,%6,%7}, {%8,%9}, {%0,%1,%2,%3};" \
        : "+f"((d)[0]), "+f"((d)[1]), "+f"((d)[2]), "+f"((d)[3]) \
        : "r"((a)[0]), "r"((a)[1]), "r"((a)[2]), "r"((a)[3]), "r"(b0v), "r"(b1v))

// SMEM tile: 128 rows x 64 f16 (128B/row, 8 x 16B chunks), conflict-free swizzle.
__device__ __forceinline__ uint32_t swz64(int row, int ch) {
    return (uint32_t)(row * 128 + ((ch ^ (row & 7)) << 4));
}

// ===================== scratch (device globals) ==========================
#define AL __align__(16)
__device__ AL __half g_Xhi[XLEN * BSZ * XD];
__device__ AL __half g_Yhi[YLEN * BSZ * YD];
__device__ AL __half g_Xkw_hi[HD * XD];
__device__ AL __half g_Xvw_hi[HD * XD];
__device__ AL __half g_Yqw_hi[HD * YD];
__device__ AL __half g_Yww_hi[YOUT * CATD];
__device__ AL __half g_xk_hi[XLEN * BSZ * HD];
__device__ AL __half g_yq_hi[YLEN * BSZ * HD];
__device__ AL __half g_xvT_hi[BSZ * HD * XLEN];
__device__ AL __half g_af_hi[YLEN * BSZ * HD];
__device__ AL __half g_lattn[BSZ * YLEN * XLEN];     // fp16 logits -> attn in place

// ===================== fused split: fp32 -> fp16 hi ======================
struct SplitArgs {
    const float* src[6];
    __half* hi[6];
    long n4[6];
};

__global__ __launch_bounds__(256) void split_all(SplitArgs s)
{
    const int e = blockIdx.y;
    long i4 = (long)blockIdx.x * 256 + threadIdx.x;
    if (i4 >= s.n4[e]) return;
    long base = i4 * 4;
    float4 v = *(const float4*)(s.src[e] + base);
    __half2 hp0 = {__float2half_rn(v.x), __float2half_rn(v.y)};
    __half2 hp1 = {__float2half_rn(v.z), __float2half_rn(v.w)};
    *(uint2*)(s.hi[e] + base) = make_uint2(*(uint32_t*)&hp0, *(uint32_t*)&hp1);
}

// ===================== softmax: fp16 logits -> fp16 attn (in place) ======
__global__ __launch_bounds__(256) void softmax_kernel()
{
    const long row = blockIdx.x;
    __half2* p = (__half2*)(g_lattn + row * XLEN);   // 1024 half2
    const int tid = threadIdx.x;

    float v[8];
#pragma unroll
    for (int i = 0; i < 4; i++) {
        float2 t = __half22float2(p[tid + (i << 8)]);
        v[i * 2] = t.x; v[i * 2 + 1] = t.y;
    }
    float mx = -FMAXV;
#pragma unroll
    for (int i = 0; i < 8; i++) mx = fmaxf(mx, v[i]);

    __shared__ float sred[8];
#pragma unroll
    for (int o = 16; o > 0; o >>= 1) mx = fmaxf(mx, __shfl_xor_sync(0xffffffff, mx, o));
    if ((tid & 31) == 0) sred[tid >> 5] = mx;
    __syncthreads();
    mx = sred[0];
#pragma unroll
    for (int w = 1; w < 8; w++) mx = fmaxf(mx, sred[w]);
    __syncthreads();

    float s = 0.0f;
#pragma unroll
    for (int i = 0; i < 8; i++) { v[i] = expf(v[i] - mx); s += v[i]; }
#pragma unroll
    for (int o = 16; o > 0; o >>= 1) s += __shfl_xor_sync(0xffffffff, s, o);
    if ((tid & 31) == 0) sred[tid >> 5] = s;
    __syncthreads();
    s = 0.0f;
#pragma unroll
    for (int w = 0; w < 8; w++) s += sred[w];

    const float inv = 1.0f / s;
#pragma unroll
    for (int i = 0; i < 4; i++) {
        __half2 h = {__float2half_rn(v[i * 2] * inv), __float2half_rn(v[i * 2 + 1] * inv)};
        p[tid + (i << 8)] = h;
    }
}

// ===================== fp16 GEMM core ====================================
// C[M,N] = Ah[M,K] @ Bh[N,K]^T
// Block 128x128, BK=64, 8 warps (2x4), warp tile 64x32, 3-stage cp.async,
// 2 CTAs/SM. Smem-staged coalesced epilogues.
// MODE 0: fp16 out (+bias col/row, scale).
// MODE 1: logits: v + sig*align, clamp, mask fill -> fp16 (into g.Chi).
// MODE 2: +bias -> fp32.  MODE 3: accumulate into fp32 C.
struct GemmArgs {
    const __half *Ah, *Bh;
    long lda, ldb, Abatch, Bbatch;
    int K;
    float* Cf;
    __half *Chi;
    long ldc, Cbatch;
    const float* bias;
    int bias_rows;
    float scale;
    const float* align;
    const int*   mask;
    const float* alignw;
};

#define STG   32768            // Ah 16K | Bh 16K
#define NSTG  3
#define EPIT  136
#define SMEM_BYTES (NSTG * STG)

template <int MODE>
__device__ __forceinline__ void gemm_body(const GemmArgs& g, int bx, int by, int b)
{
    extern __shared__ char smem[];
    const uint32_t sb = smem_u32(smem);
    const int tid = threadIdx.x, wid = tid >> 5, lane = tid & 31;
    const long m0 = (long)by * 128, n0 = (long)bx * 128;
    const int wm = (wid >> 2) * 64;
    const int wn = (wid & 3) * 32;

    const __half* Ah = g.Ah + (long)b * g.Abatch;
    const __half* Bh = g.Bh + (long)b * g.Bbatch;

    const int lrow = tid >> 3, lch = tid & 7;
    const uint32_t sw0 = swz64(lrow, lch);
    const long ga0 = (m0 + lrow) * g.lda + lch * 8;
    const long gb0 = (n0 + lrow) * g.ldb + lch * 8;
    const long astep = 32 * g.lda, bstep = 32 * g.ldb;

    const int NT = g.K >> 6;
    const int a_r = lane & 15, a_c = lane >> 4;
    const int b_r = (lane & 7) + ((lane >> 4) & 1) * 8, b_c = (lane >> 3) & 1;

    float acc[4][4][4];
#pragma unroll
    for (int i = 0; i < 4; i++)
#pragma unroll
        for (int j = 0; j < 4; j++)
#pragma unroll
            for (int k = 0; k < 4; k++) acc[i][j][k] = 0.0f;

    auto load_stage = [&](int s, int it) {
        const long k0 = (long)it << 6;
        const uint32_t base = sb + s * STG;
#pragma unroll
        for (int i = 0; i < 4; i++) {
            CP16(base + sw0 + i * 4096,         (const char*)(Ah + ga0 + i * astep + k0));
            CP16(base + 16384 + sw0 + i * 4096, (const char*)(Bh + gb0 + i * bstep + k0));
        }
        CP_COMMIT();
    };

    load_stage(0, 0);
    load_stage(1, 1);

    // warm L2 with the epilogue's gmem inputs while the mainloop runs
    if (MODE == 1) {
#pragma unroll
        for (int i = 0; i < 2; i++) {
            const int gid = tid + i * 256;           // 512 ids: 128 rows x 4 segs
            const int row = gid >> 2, seg = gid & 3;
            const long idx = (long)b * g.Cbatch + (m0 + row) * g.ldc + n0 + seg * 32;
            PREF_L2(g.align + idx);
            PREF_L2(g.mask + idx);
        }
    } else if (MODE == 3) {
#pragma unroll
        for (int i = 0; i < 2; i++) {
            const int gid = tid + i * 256;
            const int row = gid >> 2, seg = gid & 3;
            const long idx = (long)b * g.Cbatch + (m0 + row) * g.ldc + n0 + seg * 32;
            PREF_L2(g.Cf + idx);
        }
    }

    int cur = 0, nxt = 2;
    for (int it = 0; it < NT; ++it) {
        asm volatile("cp.async.wait_group 1;");
        __syncthreads();
        if (it + 2 < NT) {
            load_stage(nxt, it + 2);
            if (++nxt == NSTG) nxt = 0;
        } else CP_COMMIT();

        const uint32_t st = sb + cur * STG;
        if (++cur == NSTG) cur = 0;
#pragma unroll
        for (int ks = 0; ks < 4; ks++) {
            const int kc = ks * 2;
            uint32_t ah[4][4], bh[2][4];
#pragma unroll
            for (int mi = 0; mi < 4; mi++)
                LDSM4(ah[mi], st + swz64(wm + mi * 16 + a_r, kc + a_c));
#pragma unroll
            for (int nb = 0; nb < 2; nb++)
                LDSM4(bh[nb], st + 16384 + swz64(wn + nb * 16 + b_r, kc + b_c));
#pragma unroll
            for (int mi = 0; mi < 4; mi++)
#pragma unroll
                for (int ni = 0; ni < 4; ni++) {
                    const int nb = ni >> 1, sub = (ni & 1) * 2;
                    MMA_F16(acc[mi][ni], ah[mi], bh[nb][sub], bh[nb][sub + 1]);
                }
        }
    }
    __syncthreads();   // pipeline smem now reusable as staging

    // ---- stage acc tile to smem ----
    float* sf = (float*)smem;
#pragma unroll
    for (int mi = 0; mi < 4; mi++)
#pragma unroll
        for (int ni = 0; ni < 4; ni++) {
            const int row = wm + mi * 16 + (lane >> 2);
            const int col = wn + ni * 8 + (lane & 3) * 2;
            *(float2*)&sf[row * EPIT + col] =
                make_float2(acc[mi][ni][0], acc[mi][ni][1]);
            *(float2*)&sf[(row + 8) * EPIT + col] =
                make_float2(acc[mi][ni][2], acc[mi][ni][3]);
        }
    __syncthreads();

    // ---- thread-linear gmem phase: coalesced 16B transactions ----
    if (MODE == 0) {
        const float sc = g.scale;
#pragma unroll
        for (int i = 0; i < 8; i++) {
            const int gid = tid + i * 256;
            const int row = gid >> 4, c0 = (gid & 15) * 8;
            float4 va = *(float4*)&sf[row * EPIT + c0];
            float4 vb = *(float4*)&sf[row * EPIT + c0 + 4];
            float v[8] = {va.x, va.y, va.z, va.w, vb.x, vb.y, vb.z, vb.w};
            if (g.bias) {
                if (g.bias_rows) {
                    const float br = __ldg(&g.bias[m0 + row]);
#pragma unroll
                    for (int j = 0; j < 8; j++) v[j] += br;
                } else {
                    float4 b0 = *(const float4*)&g.bias[n0 + c0];
                    float4 b1 = *(const float4*)&g.bias[n0 + c0 + 4];
                    v[0] += b0.x; v[1] += b0.y; v[2] += b0.z; v[3] += b0.w;
                    v[4] += b1.x; v[5] += b1.y; v[6] += b1.z; v[7] += b1.w;
                }
            }
            uint4 u;
            __half2 h0 = {__float2half_rn(v[0] * sc), __float2half_rn(v[1] * sc)};
            __half2 h1 = {__float2half_rn(v[2] * sc), __float2half_rn(v[3] * sc)};
            __half2 h2 = {__float2half_rn(v[4] * sc), __float2half_rn(v[5] * sc)};
            __half2 h3 = {__float2half_rn(v[6] * sc), __float2half_rn(v[7] * sc)};
            u.x = *(uint32_t*)&h0; u.y = *(uint32_t*)&h1;
            u.z = *(uint32_t*)&h2; u.w = *(uint32_t*)&h3;
            const long idx = (long)b * g.Cbatch + (m0 + row) * g.ldc + n0 + c0;
            *(uint4*)(g.Chi + idx) = u;
        }
    } else if (MODE == 1) {
        const float sig = 1.0f / (1.0f + expf(-__ldg(g.alignw)));
#pragma unroll
        for (int i = 0; i < 8; i++) {
            const int gid = tid + i * 256;
            const int row = gid >> 4, c0 = (gid & 15) * 8;
            float4 va = *(float4*)&sf[row * EPIT + c0];
            float4 vb = *(float4*)&sf[row * EPIT + c0 + 4];
            float v[8] = {va.x, va.y, va.z, va.w, vb.x, vb.y, vb.z, vb.w};
            const long idx = (long)b * g.Cbatch + (m0 + row) * g.ldc + n0 + c0;
            float4 a0 = *(const float4*)(g.align + idx);
            float4 a1 = *(const float4*)(g.align + idx + 4);
            int4   m0v = *(const int4*)(g.mask + idx);
            int4   m1v = *(const int4*)(g.mask + idx + 4);
            float av[8] = {a0.x, a0.y, a0.z, a0.w, a1.x, a1.y, a1.z, a1.w};
            int   mv[8] = {m0v.x, m0v.y, m0v.z, m0v.w, m1v.x, m1v.y, m1v.z, m1v.w};
            __half2 hh[4];
#pragma unroll
            for (int j = 0; j < 8; j++) {
                float o = v[j] + sig * av[j];
                o = fminf(fmaxf(o, -H16MAX), H16MAX);
                if (mv[j] != 0) o = -H16MAX;
                if ((j & 1) == 0) hh[j >> 1].x = __float2half_rn(o);
                else              hh[j >> 1].y = __float2half_rn(o);
            }
            uint4 u;
            u.x = *(uint32_t*)&hh[0]; u.y = *(uint32_t*)&hh[1];
            u.z = *(uint32_t*)&hh[2]; u.w = *(uint32_t*)&hh[3];
            *(uint4*)(g.Chi + idx) = u;
        }
    } else if (MODE == 2) {
#pragma unroll
        for (int i = 0; i < 16; i++) {
            const int gid = tid + i * 256;
            const int row = gid >> 5, c0 = (gid & 31) * 4;
            float4 v = *(float4*)&sf[row * EPIT + c0];
            float4 b4 = *(const float4*)&g.bias[n0 + c0];
            const long idx = (long)b * g.Cbatch + (m0 + row) * g.ldc + n0 + c0;
            *(float4*)(g.Cf + idx) =
                make_float4(v.x + b4.x, v.y + b4.y, v.z + b4.z, v.w + b4.w);
        }
    } else {  // MODE 3: accumulate
#pragma unroll
        for (int i = 0; i < 16; i++) {
            const int gid = tid + i * 256;
            const int row = gid >> 5, c0 = (gid & 31) * 4;
            float4 v = *(float4*)&sf[row * EPIT + c0];
            const long idx = (long)b * g.Cbatch + (m0 + row) * g.ldc + n0 + c0;
            float4 o = *(float4*)(g.Cf + idx);
            *(float4*)(g.Cf + idx) =
                make_float4(v.x + o.x, v.y + o.y, v.z + o.z, v.w + o.w);
        }
    }
}

template <int MODE>
__global__ __launch_bounds__(256, 2) void mma_gemm(GemmArgs g)
{
    gemm_body<MODE>(g, blockIdx.x, blockIdx.y, blockIdx.z);
}

// merged projections (xk, yq), striped 2:1 so waves mix both
struct Gemm2 { GemmArgs a[2]; };
__global__ __launch_bounds__(256, 2) void mma_gemm_proj(Gemm2 p)
{
    const int id = blockIdx.x;         // 768 = 256 groups x {xk, xk, yq}
    const int grp = id / 3, r = id - grp * 3;
    if (r < 2) {
        const int t = grp * 2 + r;     // 0..511 : xk  (4 nblk x 128 mblk)
        gemm_body<0>(p.a[0], t & 3, t >> 2, 0);
    } else {
        const int t = grp;             // 0..255 : yq  (4 nblk x 64 mblk)
        gemm_body<0>(p.a[1], t & 3, t >> 2, 0);
    }
}

// mega: logits(1024) | xvT(512) | out1(512), striped {lg,lg,xv,o1} per 4 ids
struct Gemm3 { GemmArgs lg, xv, o1; };
__global__ __launch_bounds__(256, 2) void mma_mega(Gemm3 p)
{
    const int id = blockIdx.x;
    const int grp = id >> 2, r = id & 3;
    if (r < 2) {
        const int t = grp * 2 + r;     // 0..1023 : logits (16 x 8 x 8)
        gemm_body<1>(p.lg, t & 15, (t >> 4) & 7, t >> 7);
    } else if (r == 2) {
        const int t = grp;             // 0..511 : xvT (16 x 4 x 8)
        gemm_body<0>(p.xv, t & 15, (t >> 4) & 3, t >> 6);
    } else {
        const int t = grp;             // 0..511 : out1 (8 x 64)
        gemm_body<2>(p.o1, t & 7, t >> 3, 0);
    }
}

// ===================== launch ============================================
extern "C" void kernel_launch(void* const* d_in, const int* in_sizes, int n_in,
                              void* d_out, int out_size)
{
    const float* X         = (const float*)d_in[0];
    const float* Y         = (const float*)d_in[1];
    const float* alignment = (const float*)d_in[2];
    const int*   mask      = (const int*)d_in[3];
    const float* Xk_w      = (const float*)d_in[4];
    const float* Xk_b      = (const float*)d_in[5];
    const float* Xv_w      = (const float*)d_in[6];
    const float* Xv_b      = (const float*)d_in[7];
    const float* Yq_w      = (const float*)d_in[8];
    const float* Yq_b      = (const float*)d_in[9];
    const float* Yw_w      = (const float*)d_in[10];
    const float* Yw_b      = (const float*)d_in[11];
    const float* align_w   = (const float*)d_in[12];
    float* out = (float*)d_out;

    cudaFuncSetAttribute((const void*)mma_gemm<0>, cudaFuncAttributeMaxDynamicSharedMemorySize, SMEM_BYTES);
    cudaFuncSetAttribute((const void*)mma_gemm<3>, cudaFuncAttributeMaxDynamicSharedMemorySize, SMEM_BYTES);
    cudaFuncSetAttribute((const void*)mma_gemm_proj, cudaFuncAttributeMaxDynamicSharedMemorySize, SMEM_BYTES);
    cudaFuncSetAttribute((const void*)mma_mega, cudaFuncAttributeMaxDynamicSharedMemorySize, SMEM_BYTES);

#define SYM(p, s) do { void* _t; cudaGetSymbolAddress(&_t, s); p = (decltype(p))_t; } while (0)
    __half *Xhi, *Yhi, *Xkw_hi, *Xvw_hi, *Yqw_hi, *Yww_hi,
        *xk_hi, *yq_hi, *xvT_hi, *af_hi, *lattn;
    SYM(Xhi, g_Xhi); SYM(Yhi, g_Yhi);
    SYM(Xkw_hi, g_Xkw_hi); SYM(Xvw_hi, g_Xvw_hi);
    SYM(Yqw_hi, g_Yqw_hi); SYM(Yww_hi, g_Yww_hi);
    SYM(xk_hi, g_xk_hi); SYM(yq_hi, g_yq_hi); SYM(xvT_hi, g_xvT_hi);
    SYM(af_hi, g_af_hi); SYM(lattn, g_lattn);

    // ---- fused split (1 launch, contiguous hi-only) ----
    SplitArgs sa;
    sa.src[0] = X;    sa.hi[0] = Xhi;    sa.n4[0] = (long)XLEN * BSZ * XD / 4;
    sa.src[1] = Y;    sa.hi[1] = Yhi;    sa.n4[1] = (long)YLEN * BSZ * YD / 4;
    sa.src[2] = Xk_w; sa.hi[2] = Xkw_hi; sa.n4[2] = (long)HD * XD / 4;
    sa.src[3] = Xv_w; sa.hi[3] = Xvw_hi; sa.n4[3] = (long)HD * XD / 4;
    sa.src[4] = Yq_w; sa.hi[4] = Yqw_hi; sa.n4[4] = (long)HD * YD / 4;
    sa.src[5] = Yw_w; sa.hi[5] = Yww_hi; sa.n4[5] = (long)YOUT * CATD / 4;
    long maxn4 = sa.n4[0];
    for (int i = 1; i < 6; i++) if (sa.n4[i] > maxn4) maxn4 = sa.n4[i];
    split_all<<<dim3((unsigned)((maxn4 + 255) / 256), 6), 256>>>(sa);

    // ---- merged projections: xk, yq (striped) ----
    Gemm2 p2 = {};
    {
        GemmArgs a = {};
        a.Ah = Xhi; a.lda = XD; a.Abatch = 0;
        a.Bh = Xkw_hi; a.ldb = XD; a.Bbatch = 0;
        a.K = XD; a.Chi = xk_hi; a.ldc = HD; a.Cbatch = 0;
        a.bias = Xk_b; a.bias_rows = 0; a.scale = 1.0f;
        p2.a[0] = a;

        a.Ah = Yhi; a.lda = YD;
        a.Bh = Yqw_hi; a.ldb = YD;
        a.Chi = yq_hi; a.bias = Yq_b; a.scale = INV_SQRT_HD;
        p2.a[1] = a;
    }
    mma_gemm_proj<<<768, 256, SMEM_BYTES>>>(p2);

    // ---- mega: logits + xvT + out1 (striped 2048-block launch) ----
    Gemm3 p3 = {};
    {
        GemmArgs a = {};
        // logits: per batch M=1024(y) N=2048(x) K=512 -> fp16 in-place buffer
        a.Ah = yq_hi; a.lda = BSZ * HD; a.Abatch = HD;
        a.Bh = xk_hi; a.ldb = BSZ * HD; a.Bbatch = HD;
        a.K = HD; a.Chi = lattn; a.ldc = XLEN; a.Cbatch = (long)YLEN * XLEN;
        a.align = alignment; a.mask = mask; a.alignw = align_w; a.scale = 1.0f;
        p3.lg = a;

        // xvT[b,h,x] = Xv_w @ X[.,b,.]^T + Xv_b(row) : M=512(h) N=2048(x) K=1024
        a = {};
        a.Ah = Xvw_hi; a.lda = XD; a.Abatch = 0;
        a.Bh = Xhi; a.ldb = (long)BSZ * XD; a.Bbatch = XD;
        a.K = XD; a.Chi = xvT_hi; a.ldc = XLEN; a.Cbatch = (long)HD * XLEN;
        a.bias = Xv_b; a.bias_rows = 1; a.scale = 1.0f;
        p3.xv = a;

        // out1 = Y @ Yw[:, :YD]^T + bias : M=8192 N=1024 K=1024
        a = {};
        a.Ah = Yhi; a.lda = YD; a.Abatch = 0;
        a.Bh = Yww_hi; a.ldb = CATD; a.Bbatch = 0;
        a.K = YD; a.Cf = out; a.ldc = YOUT; a.Cbatch = 0;
        a.bias = Yw_b; a.bias_rows = 0; a.scale = 1.0f;
        p3.o1 = a;
    }
    mma_mega<<<2048, 256, SMEM_BYTES>>>(p3);

    // ---- softmax (in place, fp16) ----
    softmax_kernel<<<BSZ * YLEN, 256>>>();

    GemmArgs a = {};

    // ---- attn_feat = attn @ xvT^T -> af[(y,b),h] : per batch ----
    a.Ah = lattn; a.lda = XLEN; a.Abatch = (long)YLEN * XLEN;
    a.Bh = xvT_hi; a.ldb = XLEN; a.Bbatch = (long)HD * XLEN;
    a.K = XLEN; a.Chi = af_hi;
    a.ldc = (long)BSZ * HD; a.Cbatch = HD;
    a.bias = nullptr; a.bias_rows = 0; a.scale = 1.0f;
    mma_gemm<0><<<dim3(HD / 128, YLEN / 128, BSZ), 256, SMEM_BYTES>>>(a);

    // ---- out += af @ Yw[:, YD:]^T : M=8192 N=1024 K=512 (accumulate) ----
    a = {};
    a.Ah = af_hi; a.lda = HD; a.Abatch = 0;
    a.Bh = Yww_hi + YD; a.ldb = CATD; a.Bbatch = 0;
    a.K = HD; a.Cf = out; a.ldc = YOUT; a.Cbatch = 0;
    a.bias = nullptr; a.bias_rows = 0; a.scale = 1.0f;
    mma_gemm<3><<<dim3(YOUT / 128, YLEN * BSZ / 128, 1), 256, SMEM_BYTES>>>(a);
}

// round 15
// speedup vs baseline: 1.1061x; 1.0108x over previous
#include <cuda_runtime.h>
#include <cuda_fp16.h>
#include <math.h>
#include <stdint.h>

#define XLEN 2048
#define YLEN 1024
#define BSZ  8
#define XD   1024
#define YD   1024
#define HD   512
#define YOUT 1024
#define CATD (YD + HD)
#define FMAXV 3.402823466e38f
#define H16MAX 65504.0f
#define INV_SQRT_HD 0.04419417382415922f

// ===================== PTX helpers =====================
__device__ __forceinline__ uint32_t smem_u32(const void* p) {
    uint32_t a;
    asm("{ .reg .u64 t; cvta.to.shared.u64 t, %1; cvt.u32.u64 %0, t; }" : "=r"(a) : "l"(p));
    return a;
}
#define CP16(dst, src) \
    asm volatile("cp.async.cg.shared.global [%0], [%1], 16;" :: "r"(dst), "l"(src))
#define CP_COMMIT() asm volatile("cp.async.commit_group;")
#define PREF_L2(p) asm volatile("prefetch.global.L2 [%0];" :: "l"(p))

#define LDSM4(r, a) \
    asm volatile("ldmatrix.sync.aligned.m8n8.x4.shared.b16 {%0,%1,%2,%3}, [%4];" \
        : "=r"((r)[0]), "=r"((r)[1]), "=r"((r)[2]), "=r"((r)[3]) : "r"(a))

#define MMA_F16(d, a, b0v, b1v) \
    asm volatile("mma.sync.aligned.m16n8k16.row.col.f32.f16.f16.f32 " \
        "{%0,%1,%2,%3}, {%4,%5,%6,%7}, {%8,%9}, {%0,%1,%2,%3};" \
        : "+f"((d)[0]), "+f"((d)[1]), "+f"((d)[2]), "+f"((d)[3]) \
        : "r"((a)[0]), "r"((a)[1]), "r"((a)[2]), "r"((a)[3]), "r"(b0v), "r"(b1v))

// SMEM tile: 128 rows x 64 f16 (128B/row, 8 x 16B chunks), conflict-free swizzle.
__device__ __forceinline__ uint32_t swz64(int row, int ch) {
    return (uint32_t)(row * 128 + ((ch ^ (row & 7)) << 4));
}

// ===================== scratch (device globals) ==========================
#define AL __align__(16)
__device__ AL __half g_Xhi[XLEN * BSZ * XD];
__device__ AL __half g_Yhi[YLEN * BSZ * YD];
__device__ AL __half g_Xkw_hi[HD * XD];
__device__ AL __half g_Xvw_hi[HD * XD];
__device__ AL __half g_Yqw_hi[HD * YD];
__device__ AL __half g_Yww_hi[YOUT * CATD];
__device__ AL __half g_xk_hi[XLEN * BSZ * HD];
__device__ AL __half g_yq_hi[YLEN * BSZ * HD];
__device__ AL __half g_xvT_hi[BSZ * HD * XLEN];
__device__ AL __half g_af_hi[YLEN * BSZ * HD];
__device__ AL __half g_o1[YLEN * BSZ * YOUT];        // fp16 out1 staging
__device__ AL __half g_lattn[BSZ * YLEN * XLEN];     // fp16 logits -> attn in place

// ===================== fused split: fp32 -> fp16 hi ======================
struct SplitArgs {
    const float* src[6];
    __half* hi[6];
    long n4[6];
};

__global__ __launch_bounds__(256) void split_all(SplitArgs s)
{
    const int e = blockIdx.y;
    long i4 = (long)blockIdx.x * 256 + threadIdx.x;
    if (i4 >= s.n4[e]) return;
    long base = i4 * 4;
    float4 v = *(const float4*)(s.src[e] + base);
    __half2 hp0 = {__float2half_rn(v.x), __float2half_rn(v.y)};
    __half2 hp1 = {__float2half_rn(v.z), __float2half_rn(v.w)};
    *(uint2*)(s.hi[e] + base) = make_uint2(*(uint32_t*)&hp0, *(uint32_t*)&hp1);
}

// ===================== softmax: fp16 logits -> fp16 attn (in place) ======
// One row = 2048 halves = 4096B = 256 threads x 16B: one uint4 per thread.
__global__ __launch_bounds__(256) void softmax_kernel()
{
    const long row = blockIdx.x;
    uint4* p = (uint4*)(g_lattn + row * XLEN);
    const int tid = threadIdx.x;

    uint4 u = p[tid];
    __half2* h2 = (__half2*)&u;
    float v[8];
#pragma unroll
    for (int i = 0; i < 4; i++) {
        float2 t = __half22float2(h2[i]);
        v[i * 2] = t.x; v[i * 2 + 1] = t.y;
    }
    float mx = -FMAXV;
#pragma unroll
    for (int i = 0; i < 8; i++) mx = fmaxf(mx, v[i]);

    __shared__ float sred[8];
#pragma unroll
    for (int o = 16; o > 0; o >>= 1) mx = fmaxf(mx, __shfl_xor_sync(0xffffffff, mx, o));
    if ((tid & 31) == 0) sred[tid >> 5] = mx;
    __syncthreads();
    mx = sred[0];
#pragma unroll
    for (int w = 1; w < 8; w++) mx = fmaxf(mx, sred[w]);
    __syncthreads();

    float s = 0.0f;
#pragma unroll
    for (int i = 0; i < 8; i++) { v[i] = expf(v[i] - mx); s += v[i]; }
#pragma unroll
    for (int o = 16; o > 0; o >>= 1) s += __shfl_xor_sync(0xffffffff, s, o);
    if ((tid & 31) == 0) sred[tid >> 5] = s;
    __syncthreads();
    s = 0.0f;
#pragma unroll
    for (int w = 0; w < 8; w++) s += sred[w];

    const float inv = 1.0f / s;
#pragma unroll
    for (int i = 0; i < 4; i++) {
        __half2 h = {__float2half_rn(v[i * 2] * inv), __float2half_rn(v[i * 2 + 1] * inv)};
        h2[i] = h;
    }
    p[tid] = u;
}

// ===================== fp16 GEMM core ====================================
// C[M,N] = Ah[M,K] @ Bh[N,K]^T
// Block 128x128, BK=64, 8 warps (2x4), warp tile 64x32, 3-stage cp.async,
// 2 CTAs/SM. Smem-staged coalesced epilogues.
// MODE 0: fp16 out (+bias col/row, scale).
// MODE 1: logits: v + sig*align, clamp, mask fill -> fp16 (into g.Chi).
// MODE 2: +bias -> fp32.  MODE 3: accumulate into fp32 C.
// MODE 4: v + fp16 Cin16 -> fp32 C.
struct GemmArgs {
    const __half *Ah, *Bh;
    long lda, ldb, Abatch, Bbatch;
    int K;
    float* Cf;
    __half *Chi;
    const __half* Cin16;
    long ldc, Cbatch;
    const float* bias;
    int bias_rows;
    float scale;
    const float* align;
    const int*   mask;
    const float* alignw;
};

#define STG   32768            // Ah 16K | Bh 16K
#define NSTG  3
#define EPIT  136
#define SMEM_BYTES (NSTG * STG)

template <int MODE>
__device__ __forceinline__ void gemm_body(const GemmArgs& g, int bx, int by, int b)
{
    extern __shared__ char smem[];
    const uint32_t sb = smem_u32(smem);
    const int tid = threadIdx.x, wid = tid >> 5, lane = tid & 31;
    const long m0 = (long)by * 128, n0 = (long)bx * 128;
    const int wm = (wid >> 2) * 64;
    const int wn = (wid & 3) * 32;

    const __half* Ah = g.Ah + (long)b * g.Abatch;
    const __half* Bh = g.Bh + (long)b * g.Bbatch;

    const int lrow = tid >> 3, lch = tid & 7;
    const uint32_t sw0 = swz64(lrow, lch);
    const long ga0 = (m0 + lrow) * g.lda + lch * 8;
    const long gb0 = (n0 + lrow) * g.ldb + lch * 8;
    const long astep = 32 * g.lda, bstep = 32 * g.ldb;

    const int NT = g.K >> 6;
    const int a_r = lane & 15, a_c = lane >> 4;
    const int b_r = (lane & 7) + ((lane >> 4) & 1) * 8, b_c = (lane >> 3) & 1;

    float acc[4][4][4];
#pragma unroll
    for (int i = 0; i < 4; i++)
#pragma unroll
        for (int j = 0; j < 4; j++)
#pragma unroll
            for (int k = 0; k < 4; k++) acc[i][j][k] = 0.0f;

    auto load_stage = [&](int s, int it) {
        const long k0 = (long)it << 6;
        const uint32_t base = sb + s * STG;
#pragma unroll
        for (int i = 0; i < 4; i++) {
            CP16(base + sw0 + i * 4096,         (const char*)(Ah + ga0 + i * astep + k0));
            CP16(base + 16384 + sw0 + i * 4096, (const char*)(Bh + gb0 + i * bstep + k0));
        }
        CP_COMMIT();
    };

    load_stage(0, 0);
    load_stage(1, 1);

    // warm L2 with the epilogue's gmem inputs while the mainloop runs
    if (MODE == 1) {
#pragma unroll
        for (int i = 0; i < 2; i++) {
            const int gid = tid + i * 256;           // 512 ids: 128 rows x 4 segs
            const int row = gid >> 2, seg = gid & 3;
            const long idx = (long)b * g.Cbatch + (m0 + row) * g.ldc + n0 + seg * 32;
            PREF_L2(g.align + idx);
            PREF_L2(g.mask + idx);
        }
    } else if (MODE == 3) {
#pragma unroll
        for (int i = 0; i < 2; i++) {
            const int gid = tid + i * 256;
            const int row = gid >> 2, seg = gid & 3;
            const long idx = (long)b * g.Cbatch + (m0 + row) * g.ldc + n0 + seg * 32;
            PREF_L2(g.Cf + idx);
        }
    } else if (MODE == 4) {
        const int row = tid >> 1, seg = tid & 1;     // 256 ids: 128 rows x 2 segs
        const long idx = (long)b * g.Cbatch + (m0 + row) * g.ldc + n0 + seg * 64;
        PREF_L2(g.Cin16 + idx);
    }

    int cur = 0, nxt = 2;
    for (int it = 0; it < NT; ++it) {
        asm volatile("cp.async.wait_group 1;");
        __syncthreads();
        if (it + 2 < NT) {
            load_stage(nxt, it + 2);
            if (++nxt == NSTG) nxt = 0;
        } else CP_COMMIT();

        const uint32_t st = sb + cur * STG;
        if (++cur == NSTG) cur = 0;
#pragma unroll
        for (int ks = 0; ks < 4; ks++) {
            const int kc = ks * 2;
            uint32_t ah[4][4], bh[2][4];
#pragma unroll
            for (int mi = 0; mi < 4; mi++)
                LDSM4(ah[mi], st + swz64(wm + mi * 16 + a_r, kc + a_c));
#pragma unroll
            for (int nb = 0; nb < 2; nb++)
                LDSM4(bh[nb], st + 16384 + swz64(wn + nb * 16 + b_r, kc + b_c));
#pragma unroll
            for (int mi = 0; mi < 4; mi++)
#pragma unroll
                for (int ni = 0; ni < 4; ni++) {
                    const int nb = ni >> 1, sub = (ni & 1) * 2;
                    MMA_F16(acc[mi][ni], ah[mi], bh[nb][sub], bh[nb][sub + 1]);
                }
        }
    }
    __syncthreads();   // pipeline smem now reusable as staging

    // ---- stage acc tile to smem ----
    float* sf = (float*)smem;
#pragma unroll
    for (int mi = 0; mi < 4; mi++)
#pragma unroll
        for (int ni = 0; ni < 4; ni++) {
            const int row = wm + mi * 16 + (lane >> 2);
            const int col = wn + ni * 8 + (lane & 3) * 2;
            *(float2*)&sf[row * EPIT + col] =
                make_float2(acc[mi][ni][0], acc[mi][ni][1]);
            *(float2*)&sf[(row + 8) * EPIT + col] =
                make_float2(acc[mi][ni][2], acc[mi][ni][3]);
        }
    __syncthreads();

    // ---- thread-linear gmem phase: coalesced 16B transactions ----
    if (MODE == 0) {
        const float sc = g.scale;
#pragma unroll
        for (int i = 0; i < 8; i++) {
            const int gid = tid + i * 256;
            const int row = gid >> 4, c0 = (gid & 15) * 8;
            float4 va = *(float4*)&sf[row * EPIT + c0];
            float4 vb = *(float4*)&sf[row * EPIT + c0 + 4];
            float v[8] = {va.x, va.y, va.z, va.w, vb.x, vb.y, vb.z, vb.w};
            if (g.bias) {
                if (g.bias_rows) {
                    const float br = __ldg(&g.bias[m0 + row]);
#pragma unroll
                    for (int j = 0; j < 8; j++) v[j] += br;
                } else {
                    float4 b0 = *(const float4*)&g.bias[n0 + c0];
                    float4 b1 = *(const float4*)&g.bias[n0 + c0 + 4];
                    v[0] += b0.x; v[1] += b0.y; v[2] += b0.z; v[3] += b0.w;
                    v[4] += b1.x; v[5] += b1.y; v[6] += b1.z; v[7] += b1.w;
                }
            }
            uint4 u;
            __half2 h0 = {__float2half_rn(v[0] * sc), __float2half_rn(v[1] * sc)};
            __half2 h1 = {__float2half_rn(v[2] * sc), __float2half_rn(v[3] * sc)};
            __half2 h2 = {__float2half_rn(v[4] * sc), __float2half_rn(v[5] * sc)};
            __half2 h3 = {__float2half_rn(v[6] * sc), __float2half_rn(v[7] * sc)};
            u.x = *(uint32_t*)&h0; u.y = *(uint32_t*)&h1;
            u.z = *(uint32_t*)&h2; u.w = *(uint32_t*)&h3;
            const long idx = (long)b * g.Cbatch + (m0 + row) * g.ldc + n0 + c0;
            *(uint4*)(g.Chi + idx) = u;
        }
    } else if (MODE == 1) {
        const float sig = 1.0f / (1.0f + expf(-__ldg(g.alignw)));
#pragma unroll
        for (int i = 0; i < 8; i++) {
            const int gid = tid + i * 256;
            const int row = gid >> 4, c0 = (gid & 15) * 8;
            float4 va = *(float4*)&sf[row * EPIT + c0];
            float4 vb = *(float4*)&sf[row * EPIT + c0 + 4];
            float v[8] = {va.x, va.y, va.z, va.w, vb.x, vb.y, vb.z, vb.w};
            const long idx = (long)b * g.Cbatch + (m0 + row) * g.ldc + n0 + c0;
            float4 a0 = *(const float4*)(g.align + idx);
            float4 a1 = *(const float4*)(g.align + idx + 4);
            int4   m0v = *(const int4*)(g.mask + idx);
            int4   m1v = *(const int4*)(g.mask + idx + 4);
            float av[8] = {a0.x, a0.y, a0.z, a0.w, a1.x, a1.y, a1.z, a1.w};
            int   mv[8] = {m0v.x, m0v.y, m0v.z, m0v.w, m1v.x, m1v.y, m1v.z, m1v.w};
            __half2 hh[4];
#pragma unroll
            for (int j = 0; j < 8; j++) {
                float o = v[j] + sig * av[j];
                o = fminf(fmaxf(o, -H16MAX), H16MAX);
                if (mv[j] != 0) o = -H16MAX;
                if ((j & 1) == 0) hh[j >> 1].x = __float2half_rn(o);
                else              hh[j >> 1].y = __float2half_rn(o);
            }
            uint4 u;
            u.x = *(uint32_t*)&hh[0]; u.y = *(uint32_t*)&hh[1];
            u.z = *(uint32_t*)&hh[2]; u.w = *(uint32_t*)&hh[3];
            *(uint4*)(g.Chi + idx) = u;
        }
    } else if (MODE == 2) {
#pragma unroll
        for (int i = 0; i < 16; i++) {
            const int gid = tid + i * 256;
            const int row = gid >> 5, c0 = (gid & 31) * 4;
            float4 v = *(float4*)&sf[row * EPIT + c0];
            float4 b4 = *(const float4*)&g.bias[n0 + c0];
            const long idx = (long)b * g.Cbatch + (m0 + row) * g.ldc + n0 + c0;
            *(float4*)(g.Cf + idx) =
                make_float4(v.x + b4.x, v.y + b4.y, v.z + b4.z, v.w + b4.w);
        }
    } else if (MODE == 3) {
#pragma unroll
        for (int i = 0; i < 16; i++) {
            const int gid = tid + i * 256;
            const int row = gid >> 5, c0 = (gid & 31) * 4;
            float4 v = *(float4*)&sf[row * EPIT + c0];
            const long idx = (long)b * g.Cbatch + (m0 + row) * g.ldc + n0 + c0;
            float4 o = *(float4*)(g.Cf + idx);
            *(float4*)(g.Cf + idx) =
                make_float4(v.x + o.x, v.y + o.y, v.z + o.z, v.w + o.w);
        }
    } else {  // MODE 4: v + fp16 Cin16 -> fp32
#pragma unroll
        for (int i = 0; i < 8; i++) {
            const int gid = tid + i * 256;
            const int row = gid >> 4, c0 = (gid & 15) * 8;
            float4 va = *(float4*)&sf[row * EPIT + c0];
            float4 vb = *(float4*)&sf[row * EPIT + c0 + 4];
            const long idx = (long)b * g.Cbatch + (m0 + row) * g.ldc + n0 + c0;
            uint4 hv = *(const uint4*)(g.Cin16 + idx);
            __half2* hh = (__half2*)&hv;
            float2 f0 = __half22float2(hh[0]);
            float2 f1 = __half22float2(hh[1]);
            float2 f2 = __half22float2(hh[2]);
            float2 f3 = __half22float2(hh[3]);
            *(float4*)(g.Cf + idx) =
                make_float4(va.x + f0.x, va.y + f0.y, va.z + f1.x, va.w + f1.y);
            *(float4*)(g.Cf + idx + 4) =
                make_float4(vb.x + f2.x, vb.y + f2.y, vb.z + f3.x, vb.w + f3.y);
        }
    }
}

template <int MODE>
__global__ __launch_bounds__(256, 2) void mma_gemm(GemmArgs g)
{
    gemm_body<MODE>(g, blockIdx.x, blockIdx.y, blockIdx.z);
}

// merged projections (xk, yq), striped 2:1 so waves mix both
struct Gemm2 { GemmArgs a[2]; };
__global__ __launch_bounds__(256, 2) void mma_gemm_proj(Gemm2 p)
{
    const int id = blockIdx.x;         // 768 = 256 groups x {xk, xk, yq}
    const int grp = id / 3, r = id - grp * 3;
    if (r < 2) {
        const int t = grp * 2 + r;     // 0..511 : xk  (4 nblk x 128 mblk)
        gemm_body<0>(p.a[0], t & 3, t >> 2, 0);
    } else {
        const int t = grp;             // 0..255 : yq  (4 nblk x 64 mblk)
        gemm_body<0>(p.a[1], t & 3, t >> 2, 0);
    }
}

// mega: logits(1024) | xvT(512) | out1(512), striped {lg,lg,xv,o1} per 4 ids
struct Gemm3 { GemmArgs lg, xv, o1; };
__global__ __launch_bounds__(256, 2) void mma_mega(Gemm3 p)
{
    const int id = blockIdx.x;
    const int grp = id >> 2, r = id & 3;
    if (r < 2) {
        const int t = grp * 2 + r;     // 0..1023 : logits (16 x 8 x 8)
        gemm_body<1>(p.lg, t & 15, (t >> 4) & 7, t >> 7);
    } else if (r == 2) {
        const int t = grp;             // 0..511 : xvT — by fastest for B-tile L2 reuse
        gemm_body<0>(p.xv, (t >> 2) & 15, t & 3, t >> 6);
    } else {
        const int t = grp;             // 0..511 : out1 (8 x 64) -> fp16 o1
        gemm_body<0>(p.o1, t & 7, t >> 3, 0);
    }
}

// ===================== launch ============================================
extern "C" void kernel_launch(void* const* d_in, const int* in_sizes, int n_in,
                              void* d_out, int out_size)
{
    const float* X         = (const float*)d_in[0];
    const float* Y         = (const float*)d_in[1];
    const float* alignment = (const float*)d_in[2];
    const int*   mask      = (const int*)d_in[3];
    const float* Xk_w      = (const float*)d_in[4];
    const float* Xk_b      = (const float*)d_in[5];
    const float* Xv_w      = (const float*)d_in[6];
    const float* Xv_b      = (const float*)d_in[7];
    const float* Yq_w      = (const float*)d_in[8];
    const float* Yq_b      = (const float*)d_in[9];
    const float* Yw_w      = (const float*)d_in[10];
    const float* Yw_b      = (const float*)d_in[11];
    const float* align_w   = (const float*)d_in[12];
    float* out = (float*)d_out;

    cudaFuncSetAttribute((const void*)mma_gemm<0>, cudaFuncAttributeMaxDynamicSharedMemorySize, SMEM_BYTES);
    cudaFuncSetAttribute((const void*)mma_gemm<4>, cudaFuncAttributeMaxDynamicSharedMemorySize, SMEM_BYTES);
    cudaFuncSetAttribute((const void*)mma_gemm_proj, cudaFuncAttributeMaxDynamicSharedMemorySize, SMEM_BYTES);
    cudaFuncSetAttribute((const void*)mma_mega, cudaFuncAttributeMaxDynamicSharedMemorySize, SMEM_BYTES);

#define SYM(p, s) do { void* _t; cudaGetSymbolAddress(&_t, s); p = (decltype(p))_t; } while (0)
    __half *Xhi, *Yhi, *Xkw_hi, *Xvw_hi, *Yqw_hi, *Yww_hi,
        *xk_hi, *yq_hi, *xvT_hi, *af_hi, *lattn, *o1p;
    SYM(Xhi, g_Xhi); SYM(Yhi, g_Yhi);
    SYM(Xkw_hi, g_Xkw_hi); SYM(Xvw_hi, g_Xvw_hi);
    SYM(Yqw_hi, g_Yqw_hi); SYM(Yww_hi, g_Yww_hi);
    SYM(xk_hi, g_xk_hi); SYM(yq_hi, g_yq_hi); SYM(xvT_hi, g_xvT_hi);
    SYM(af_hi, g_af_hi); SYM(lattn, g_lattn); SYM(o1p, g_o1);

    // ---- fused split (1 launch, contiguous hi-only) ----
    SplitArgs sa;
    sa.src[0] = X;    sa.hi[0] = Xhi;    sa.n4[0] = (long)XLEN * BSZ * XD / 4;
    sa.src[1] = Y;    sa.hi[1] = Yhi;    sa.n4[1] = (long)YLEN * BSZ * YD / 4;
    sa.src[2] = Xk_w; sa.hi[2] = Xkw_hi; sa.n4[2] = (long)HD * XD / 4;
    sa.src[3] = Xv_w; sa.hi[3] = Xvw_hi; sa.n4[3] = (long)HD * XD / 4;
    sa.src[4] = Yq_w; sa.hi[4] = Yqw_hi; sa.n4[4] = (long)HD * YD / 4;
    sa.src[5] = Yw_w; sa.hi[5] = Yww_hi; sa.n4[5] = (long)YOUT * CATD / 4;
    long maxn4 = sa.n4[0];
    for (int i = 1; i < 6; i++) if (sa.n4[i] > maxn4) maxn4 = sa.n4[i];
    split_all<<<dim3((unsigned)((maxn4 + 255) / 256), 6), 256>>>(sa);

    // ---- merged projections: xk, yq (striped) ----
    Gemm2 p2 = {};
    {
        GemmArgs a = {};
        a.Ah = Xhi; a.lda = XD; a.Abatch = 0;
        a.Bh = Xkw_hi; a.ldb = XD; a.Bbatch = 0;
        a.K = XD; a.Chi = xk_hi; a.ldc = HD; a.Cbatch = 0;
        a.bias = Xk_b; a.bias_rows = 0; a.scale = 1.0f;
        p2.a[0] = a;

        a.Ah = Yhi; a.lda = YD;
        a.Bh = Yqw_hi; a.ldb = YD;
        a.Chi = yq_hi; a.bias = Yq_b; a.scale = INV_SQRT_HD;
        p2.a[1] = a;
    }
    mma_gemm_proj<<<768, 256, SMEM_BYTES>>>(p2);

    // ---- mega: logits + xvT + out1 (striped 2048-block launch) ----
    Gemm3 p3 = {};
    {
        GemmArgs a = {};
        // logits: per batch M=1024(y) N=2048(x) K=512 -> fp16 in-place buffer
        a.Ah = yq_hi; a.lda = BSZ * HD; a.Abatch = HD;
        a.Bh = xk_hi; a.ldb = BSZ * HD; a.Bbatch = HD;
        a.K = HD; a.Chi = lattn; a.ldc = XLEN; a.Cbatch = (long)YLEN * XLEN;
        a.align = alignment; a.mask = mask; a.alignw = align_w; a.scale = 1.0f;
        p3.lg = a;

        // xvT[b,h,x] = Xv_w @ X[.,b,.]^T + Xv_b(row) : M=512(h) N=2048(x) K=1024
        a = {};
        a.Ah = Xvw_hi; a.lda = XD; a.Abatch = 0;
        a.Bh = Xhi; a.ldb = (long)BSZ * XD; a.Bbatch = XD;
        a.K = XD; a.Chi = xvT_hi; a.ldc = XLEN; a.Cbatch = (long)HD * XLEN;
        a.bias = Xv_b; a.bias_rows = 1; a.scale = 1.0f;
        p3.xv = a;

        // out1 = Y @ Yw[:, :YD]^T + bias : M=8192 N=1024 K=1024 -> fp16 o1
        a = {};
        a.Ah = Yhi; a.lda = YD; a.Abatch = 0;
        a.Bh = Yww_hi; a.ldb = CATD; a.Bbatch = 0;
        a.K = YD; a.Chi = o1p; a.ldc = YOUT; a.Cbatch = 0;
        a.bias = Yw_b; a.bias_rows = 0; a.scale = 1.0f;
        p3.o1 = a;
    }
    mma_mega<<<2048, 256, SMEM_BYTES>>>(p3);

    // ---- softmax (in place, fp16, vectorized) ----
    softmax_kernel<<<BSZ * YLEN, 256>>>();

    GemmArgs a = {};

    // ---- attn_feat = attn @ xvT^T -> af[(y,b),h] : per batch ----
    a.Ah = lattn; a.lda = XLEN; a.Abatch = (long)YLEN * XLEN;
    a.Bh = xvT_hi; a.ldb = XLEN; a.Bbatch = (long)HD * XLEN;
    a.K = XLEN; a.Chi = af_hi;
    a.ldc = (long)BSZ * HD; a.Cbatch = HD;
    a.bias = nullptr; a.bias_rows = 0; a.scale = 1.0f;
    mma_gemm<0><<<dim3(HD / 128, YLEN / 128, BSZ), 256, SMEM_BYTES>>>(a);

    // ---- out = o1 + af @ Yw[:, YD:]^T : M=8192 N=1024 K=512 ----
    a = {};
    a.Ah = af_hi; a.lda = HD; a.Abatch = 0;
    a.Bh = Yww_hi + YD; a.ldb = CATD; a.Bbatch = 0;
    a.K = HD; a.Cf = out; a.Cin16 = o1p; a.ldc = YOUT; a.Cbatch = 0;
    a.bias = nullptr; a.bias_rows = 0; a.scale = 1.0f;
    mma_gemm<4><<<dim3(YOUT / 128, YLEN * BSZ / 128, 1), 256, SMEM_BYTES>>>(a);
}

// round 16
// speedup vs baseline: 1.2106x; 1.0945x over previous
#include <cuda_runtime.h>
#include <cuda_fp16.h>
#include <math.h>
#include <stdint.h>

#define XLEN 2048
#define YLEN 1024
#define BSZ  8
#define XD   1024
#define YD   1024
#define HD   512
#define YOUT 1024
#define CATD (YD + HD)
#define FMAXV 3.402823466e38f
#define H16MAX 65504.0f
#define INV_SQRT_HD 0.04419417382415922f

// ===================== PTX helpers =====================
__device__ __forceinline__ uint32_t smem_u32(const void* p) {
    uint32_t a;
    asm("{ .reg .u64 t; cvta.to.shared.u64 t, %1; cvt.u32.u64 %0, t; }" : "=r"(a) : "l"(p));
    return a;
}
#define CP16(dst, src) \
    asm volatile("cp.async.cg.shared.global [%0], [%1], 16;" :: "r"(dst), "l"(src))
#define CP_COMMIT() asm volatile("cp.async.commit_group;")
#define PREF_L2(p) asm volatile("prefetch.global.L2 [%0];" :: "l"(p))

#define LDSM4(r, a) \
    asm volatile("ldmatrix.sync.aligned.m8n8.x4.shared.b16 {%0,%1,%2,%3}, [%4];" \
        : "=r"((r)[0]), "=r"((r)[1]), "=r"((r)[2]), "=r"((r)[3]) : "r"(a))

#define MMA_F16(d, a, b0v, b1v) \
    asm volatile("mma.sync.aligned.m16n8k16.row.col.f32.f16.f16.f32 " \
        "{%0,%1,%2,%3}, {%4,%5,%6,%7}, {%8,%9}, {%0,%1,%2,%3};" \
        : "+f"((d)[0]), "+f"((d)[1]), "+f"((d)[2]), "+f"((d)[3]) \
        : "r"((a)[0]), "r"((a)[1]), "r"((a)[2]), "r"((a)[3]), "r"(b0v), "r"(b1v))

// SMEM tile: 128 rows x 64 f16 (128B/row, 8 x 16B chunks), conflict-free swizzle.
__device__ __forceinline__ uint32_t swz64(int row, int ch) {
    return (uint32_t)(row * 128 + ((ch ^ (row & 7)) << 4));
}

// ===================== scratch (device globals) ==========================
#define AL __align__(16)
__device__ AL __half g_Xhi[XLEN * BSZ * XD];
__device__ AL __half g_Yhi[YLEN * BSZ * YD];
__device__ AL __half g_Xkw_hi[HD * XD];
__device__ AL __half g_Xvw_hi[HD * XD];
__device__ AL __half g_Yqw_hi[HD * YD];
__device__ AL __half g_Yww_hi[YOUT * CATD];
__device__ AL __half g_xk_hi[XLEN * BSZ * HD];
__device__ AL __half g_yq_hi[YLEN * BSZ * HD];
__device__ AL __half g_xvT_hi[BSZ * HD * XLEN];
__device__ AL __half g_af_hi[YLEN * BSZ * HD];
__device__ AL __half g_o1[YLEN * BSZ * YOUT];        // fp16 out1 staging
__device__ AL __half g_lattn[BSZ * YLEN * XLEN];     // fp16 logits -> attn in place

// ===================== fused split: fp32 -> fp16 hi (compact grid) =======
struct SplitArgs {
    const float* src[6];
    __half* hi[6];
    long n4[6];
    long blk_off[7];     // prefix of block counts per tensor
};

__global__ __launch_bounds__(256) void split_all(SplitArgs s)
{
    const long bid = blockIdx.x;
    int e = 0;
#pragma unroll
    for (int i = 1; i < 6; i++) if (bid >= s.blk_off[i]) e = i;
    long i4 = (bid - s.blk_off[e]) * 256 + threadIdx.x;
    if (i4 >= s.n4[e]) return;
    long base = i4 * 4;
    float4 v = *(const float4*)(s.src[e] + base);
    __half2 hp0 = {__float2half_rn(v.x), __float2half_rn(v.y)};
    __half2 hp1 = {__float2half_rn(v.z), __float2half_rn(v.w)};
    *(uint2*)(s.hi[e] + base) = make_uint2(*(uint32_t*)&hp0, *(uint32_t*)&hp1);
}

// ===================== softmax: fp16 logits -> fp16 attn (in place) ======
// One row = 2048 halves = 4096B = 256 threads x 16B: one uint4 per thread.
__global__ __launch_bounds__(256) void softmax_kernel()
{
    const long row = blockIdx.x;
    uint4* p = (uint4*)(g_lattn + row * XLEN);
    const int tid = threadIdx.x;

    uint4 u = p[tid];
    __half2* h2 = (__half2*)&u;
    float v[8];
#pragma unroll
    for (int i = 0; i < 4; i++) {
        float2 t = __half22float2(h2[i]);
        v[i * 2] = t.x; v[i * 2 + 1] = t.y;
    }
    float mx = -FMAXV;
#pragma unroll
    for (int i = 0; i < 8; i++) mx = fmaxf(mx, v[i]);

    __shared__ float sred[8];
#pragma unroll
    for (int o = 16; o > 0; o >>= 1) mx = fmaxf(mx, __shfl_xor_sync(0xffffffff, mx, o));
    if ((tid & 31) == 0) sred[tid >> 5] = mx;
    __syncthreads();
    mx = sred[0];
#pragma unroll
    for (int w = 1; w < 8; w++) mx = fmaxf(mx, sred[w]);
    __syncthreads();

    float s = 0.0f;
#pragma unroll
    for (int i = 0; i < 8; i++) { v[i] = __expf(v[i] - mx); s += v[i]; }
#pragma unroll
    for (int o = 16; o > 0; o >>= 1) s += __shfl_xor_sync(0xffffffff, s, o);
    if ((tid & 31) == 0) sred[tid >> 5] = s;
    __syncthreads();
    s = 0.0f;
#pragma unroll
    for (int w = 0; w < 8; w++) s += sred[w];

    const float inv = __fdividef(1.0f, s);
#pragma unroll
    for (int i = 0; i < 4; i++) {
        __half2 h = {__float2half_rn(v[i * 2] * inv), __float2half_rn(v[i * 2 + 1] * inv)};
        h2[i] = h;
    }
    p[tid] = u;
}

// ===================== fp16 GEMM core ====================================
// C[M,N] = Ah[M,K] @ Bh[N,K]^T
// Block 128x128, BK=64, 8 warps (2x4), warp tile 64x32, 3-stage cp.async,
// 2 CTAs/SM. Smem-staged coalesced epilogues.
// MODE 0: fp16 out (+bias col/row, scale).
// MODE 1: logits: v + sig*align, clamp, mask fill -> fp16 (into g.Chi).
// MODE 2: +bias -> fp32.  MODE 3: accumulate into fp32 C.
// MODE 4: v + fp16 Cin16 -> fp32 C.
struct GemmArgs {
    const __half *Ah, *Bh;
    long lda, ldb, Abatch, Bbatch;
    int K;
    float* Cf;
    __half *Chi;
    const __half* Cin16;
    long ldc, Cbatch;
    const float* bias;
    int bias_rows;
    float scale;
    const float* align;
    const int*   mask;
    const float* alignw;
};

#define STG   32768            // Ah 16K | Bh 16K
#define NSTG  3
#define EPIT  136
#define SMEM_BYTES (NSTG * STG)

template <int MODE>
__device__ __forceinline__ void gemm_body(const GemmArgs& g, int bx, int by, int b)
{
    extern __shared__ char smem[];
    const uint32_t sb = smem_u32(smem);
    const int tid = threadIdx.x, wid = tid >> 5, lane = tid & 31;
    const long m0 = (long)by * 128, n0 = (long)bx * 128;
    const int wm = (wid >> 2) * 64;
    const int wn = (wid & 3) * 32;

    const __half* Ah = g.Ah + (long)b * g.Abatch;
    const __half* Bh = g.Bh + (long)b * g.Bbatch;

    const int lrow = tid >> 3, lch = tid & 7;
    const uint32_t sw0 = swz64(lrow, lch);
    const long ga0 = (m0 + lrow) * g.lda + lch * 8;
    const long gb0 = (n0 + lrow) * g.ldb + lch * 8;
    const long astep = 32 * g.lda, bstep = 32 * g.ldb;

    const int NT = g.K >> 6;
    const int a_r = lane & 15, a_c = lane >> 4;
    const int b_r = (lane & 7) + ((lane >> 4) & 1) * 8, b_c = (lane >> 3) & 1;

    float acc[4][4][4];
#pragma unroll
    for (int i = 0; i < 4; i++)
#pragma unroll
        for (int j = 0; j < 4; j++)
#pragma unroll
            for (int k = 0; k < 4; k++) acc[i][j][k] = 0.0f;

    auto load_stage = [&](int s, int it) {
        const long k0 = (long)it << 6;
        const uint32_t base = sb + s * STG;
#pragma unroll
        for (int i = 0; i < 4; i++) {
            CP16(base + sw0 + i * 4096,         (const char*)(Ah + ga0 + i * astep + k0));
            CP16(base + 16384 + sw0 + i * 4096, (const char*)(Bh + gb0 + i * bstep + k0));
        }
        CP_COMMIT();
    };

    load_stage(0, 0);
    load_stage(1, 1);

    // warm L2 with the epilogue's gmem inputs while the mainloop runs
    if (MODE == 1) {
#pragma unroll
        for (int i = 0; i < 2; i++) {
            const int gid = tid + i * 256;           // 512 ids: 128 rows x 4 segs
            const int row = gid >> 2, seg = gid & 3;
            const long idx = (long)b * g.Cbatch + (m0 + row) * g.ldc + n0 + seg * 32;
            PREF_L2(g.align + idx);
            PREF_L2(g.mask + idx);
        }
    } else if (MODE == 3) {
#pragma unroll
        for (int i = 0; i < 2; i++) {
            const int gid = tid + i * 256;
            const int row = gid >> 2, seg = gid & 3;
            const long idx = (long)b * g.Cbatch + (m0 + row) * g.ldc + n0 + seg * 32;
            PREF_L2(g.Cf + idx);
        }
    } else if (MODE == 4) {
        const int row = tid >> 1, seg = tid & 1;     // 256 ids: 128 rows x 2 segs
        const long idx = (long)b * g.Cbatch + (m0 + row) * g.ldc + n0 + seg * 64;
        PREF_L2(g.Cin16 + idx);
    }

    int cur = 0, nxt = 2;
    for (int it = 0; it < NT; ++it) {
        asm volatile("cp.async.wait_group 1;");
        __syncthreads();
        if (it + 2 < NT) {
            load_stage(nxt, it + 2);
            if (++nxt == NSTG) nxt = 0;
        } else CP_COMMIT();

        const uint32_t st = sb + cur * STG;
        if (++cur == NSTG) cur = 0;
#pragma unroll
        for (int ks = 0; ks < 4; ks++) {
            const int kc = ks * 2;
            uint32_t ah[4][4], bh[2][4];
#pragma unroll
            for (int mi = 0; mi < 4; mi++)
                LDSM4(ah[mi], st + swz64(wm + mi * 16 + a_r, kc + a_c));
#pragma unroll
            for (int nb = 0; nb < 2; nb++)
                LDSM4(bh[nb], st + 16384 + swz64(wn + nb * 16 + b_r, kc + b_c));
#pragma unroll
            for (int mi = 0; mi < 4; mi++)
#pragma unroll
                for (int ni = 0; ni < 4; ni++) {
                    const int nb = ni >> 1, sub = (ni & 1) * 2;
                    MMA_F16(acc[mi][ni], ah[mi], bh[nb][sub], bh[nb][sub + 1]);
                }
        }
    }
    __syncthreads();   // pipeline smem now reusable as staging

    // ---- stage acc tile to smem ----
    float* sf = (float*)smem;
#pragma unroll
    for (int mi = 0; mi < 4; mi++)
#pragma unroll
        for (int ni = 0; ni < 4; ni++) {
            const int row = wm + mi * 16 + (lane >> 2);
            const int col = wn + ni * 8 + (lane & 3) * 2;
            *(float2*)&sf[row * EPIT + col] =
                make_float2(acc[mi][ni][0], acc[mi][ni][1]);
            *(float2*)&sf[(row + 8) * EPIT + col] =
                make_float2(acc[mi][ni][2], acc[mi][ni][3]);
        }
    __syncthreads();

    // ---- thread-linear gmem phase: coalesced 16B transactions ----
    if (MODE == 0) {
        const float sc = g.scale;
#pragma unroll
        for (int i = 0; i < 8; i++) {
            const int gid = tid + i * 256;
            const int row = gid >> 4, c0 = (gid & 15) * 8;
            float4 va = *(float4*)&sf[row * EPIT + c0];
            float4 vb = *(float4*)&sf[row * EPIT + c0 + 4];
            float v[8] = {va.x, va.y, va.z, va.w, vb.x, vb.y, vb.z, vb.w};
            if (g.bias) {
                if (g.bias_rows) {
                    const float br = __ldg(&g.bias[m0 + row]);
#pragma unroll
                    for (int j = 0; j < 8; j++) v[j] += br;
                } else {
                    float4 b0 = *(const float4*)&g.bias[n0 + c0];
                    float4 b1 = *(const float4*)&g.bias[n0 + c0 + 4];
                    v[0] += b0.x; v[1] += b0.y; v[2] += b0.z; v[3] += b0.w;
                    v[4] += b1.x; v[5] += b1.y; v[6] += b1.z; v[7] += b1.w;
                }
            }
            uint4 u;
            __half2 h0 = {__float2half_rn(v[0] * sc), __float2half_rn(v[1] * sc)};
            __half2 h1 = {__float2half_rn(v[2] * sc), __float2half_rn(v[3] * sc)};
            __half2 h2 = {__float2half_rn(v[4] * sc), __float2half_rn(v[5] * sc)};
            __half2 h3 = {__float2half_rn(v[6] * sc), __float2half_rn(v[7] * sc)};
            u.x = *(uint32_t*)&h0; u.y = *(uint32_t*)&h1;
            u.z = *(uint32_t*)&h2; u.w = *(uint32_t*)&h3;
            const long idx = (long)b * g.Cbatch + (m0 + row) * g.ldc + n0 + c0;
            *(uint4*)(g.Chi + idx) = u;
        }
    } else if (MODE == 1) {
        const float sig = 1.0f / (1.0f + __expf(-__ldg(g.alignw)));
#pragma unroll
        for (int i = 0; i < 8; i++) {
            const int gid = tid + i * 256;
            const int row = gid >> 4, c0 = (gid & 15) * 8;
            float4 va = *(float4*)&sf[row * EPIT + c0];
            float4 vb = *(float4*)&sf[row * EPIT + c0 + 4];
            float v[8] = {va.x, va.y, va.z, va.w, vb.x, vb.y, vb.z, vb.w};
            const long idx = (long)b * g.Cbatch + (m0 + row) * g.ldc + n0 + c0;
            float4 a0 = *(const float4*)(g.align + idx);
            float4 a1 = *(const float4*)(g.align + idx + 4);
            int4   m0v = *(const int4*)(g.mask + idx);
            int4   m1v = *(const int4*)(g.mask + idx + 4);
            float av[8] = {a0.x, a0.y, a0.z, a0.w, a1.x, a1.y, a1.z, a1.w};
            int   mv[8] = {m0v.x, m0v.y, m0v.z, m0v.w, m1v.x, m1v.y, m1v.z, m1v.w};
            __half2 hh[4];
#pragma unroll
            for (int j = 0; j < 8; j++) {
                float o = v[j] + sig * av[j];
                o = fminf(fmaxf(o, -H16MAX), H16MAX);
                if (mv[j] != 0) o = -H16MAX;
                if ((j & 1) == 0) hh[j >> 1].x = __float2half_rn(o);
                else              hh[j >> 1].y = __float2half_rn(o);
            }
            uint4 u;
            u.x = *(uint32_t*)&hh[0]; u.y = *(uint32_t*)&hh[1];
            u.z = *(uint32_t*)&hh[2]; u.w = *(uint32_t*)&hh[3];
            *(uint4*)(g.Chi + idx) = u;
        }
    } else if (MODE == 2) {
#pragma unroll
        for (int i = 0; i < 16; i++) {
            const int gid = tid + i * 256;
            const int row = gid >> 5, c0 = (gid & 31) * 4;
            float4 v = *(float4*)&sf[row * EPIT + c0];
            float4 b4 = *(const float4*)&g.bias[n0 + c0];
            const long idx = (long)b * g.Cbatch + (m0 + row) * g.ldc + n0 + c0;
            *(float4*)(g.Cf + idx) =
                make_float4(v.x + b4.x, v.y + b4.y, v.z + b4.z, v.w + b4.w);
        }
    } else if (MODE == 3) {
#pragma unroll
        for (int i = 0; i < 16; i++) {
            const int gid = tid + i * 256;
            const int row = gid >> 5, c0 = (gid & 31) * 4;
            float4 v = *(float4*)&sf[row * EPIT + c0];
            const long idx = (long)b * g.Cbatch + (m0 + row) * g.ldc + n0 + c0;
            float4 o = *(float4*)(g.Cf + idx);
            *(float4*)(g.Cf + idx) =
                make_float4(v.x + o.x, v.y + o.y, v.z + o.z, v.w + o.w);
        }
    } else {  // MODE 4: v + fp16 Cin16 -> fp32
#pragma unroll
        for (int i = 0; i < 8; i++) {
            const int gid = tid + i * 256;
            const int row = gid >> 4, c0 = (gid & 15) * 8;
            float4 va = *(float4*)&sf[row * EPIT + c0];
            float4 vb = *(float4*)&sf[row * EPIT + c0 + 4];
            const long idx = (long)b * g.Cbatch + (m0 + row) * g.ldc + n0 + c0;
            uint4 hv = *(const uint4*)(g.Cin16 + idx);
            __half2* hh = (__half2*)&hv;
            float2 f0 = __half22float2(hh[0]);
            float2 f1 = __half22float2(hh[1]);
            float2 f2 = __half22float2(hh[2]);
            float2 f3 = __half22float2(hh[3]);
            *(float4*)(g.Cf + idx) =
                make_float4(va.x + f0.x, va.y + f0.y, va.z + f1.x, va.w + f1.y);
            *(float4*)(g.Cf + idx + 4) =
                make_float4(vb.x + f2.x, vb.y + f2.y, vb.z + f3.x, vb.w + f3.y);
        }
    }
}

template <int MODE>
__global__ __launch_bounds__(256, 2) void mma_gemm(GemmArgs g)
{
    gemm_body<MODE>(g, blockIdx.x, blockIdx.y, blockIdx.z);
}

// merged projections (xk, yq), striped 2:1 so waves mix both
struct Gemm2 { GemmArgs a[2]; };
__global__ __launch_bounds__(256, 2) void mma_gemm_proj(Gemm2 p)
{
    const int id = blockIdx.x;         // 768 = 256 groups x {xk, xk, yq}
    const int grp = id / 3, r = id - grp * 3;
    if (r < 2) {
        const int t = grp * 2 + r;     // 0..511 : xk  (4 nblk x 128 mblk)
        gemm_body<0>(p.a[0], t & 3, t >> 2, 0);
    } else {
        const int t = grp;             // 0..255 : yq  (4 nblk x 64 mblk)
        gemm_body<0>(p.a[1], t & 3, t >> 2, 0);
    }
}

// mega: logits(1024) | xvT(512) | out1(512), striped {lg,lg,xv,o1} per 4 ids
struct Gemm3 { GemmArgs lg, xv, o1; };
__global__ __launch_bounds__(256, 2) void mma_mega(Gemm3 p)
{
    const int id = blockIdx.x;
    const int grp = id >> 2, r = id & 3;
    if (r < 2) {
        const int t = grp * 2 + r;     // 0..1023 : logits (16 x 8 x 8)
        gemm_body<1>(p.lg, t & 15, (t >> 4) & 7, t >> 7);
    } else if (r == 2) {
        const int t = grp;             // 0..511 : xvT — by fastest for B-tile L2 reuse
        gemm_body<0>(p.xv, (t >> 2) & 15, t & 3, t >> 6);
    } else {
        const int t = grp;             // 0..511 : out1 (8 x 64) -> fp16 o1
        gemm_body<0>(p.o1, t & 7, t >> 3, 0);
    }
}

// ===================== launch ============================================
extern "C" void kernel_launch(void* const* d_in, const int* in_sizes, int n_in,
                              void* d_out, int out_size)
{
    const float* X         = (const float*)d_in[0];
    const float* Y         = (const float*)d_in[1];
    const float* alignment = (const float*)d_in[2];
    const int*   mask      = (const int*)d_in[3];
    const float* Xk_w      = (const float*)d_in[4];
    const float* Xk_b      = (const float*)d_in[5];
    const float* Xv_w      = (const float*)d_in[6];
    const float* Xv_b      = (const float*)d_in[7];
    const float* Yq_w      = (const float*)d_in[8];
    const float* Yq_b      = (const float*)d_in[9];
    const float* Yw_w      = (const float*)d_in[10];
    const float* Yw_b      = (const float*)d_in[11];
    const float* align_w   = (const float*)d_in[12];
    float* out = (float*)d_out;

    cudaFuncSetAttribute((const void*)mma_gemm<0>, cudaFuncAttributeMaxDynamicSharedMemorySize, SMEM_BYTES);
    cudaFuncSetAttribute((const void*)mma_gemm<4>, cudaFuncAttributeMaxDynamicSharedMemorySize, SMEM_BYTES);
    cudaFuncSetAttribute((const void*)mma_gemm_proj, cudaFuncAttributeMaxDynamicSharedMemorySize, SMEM_BYTES);
    cudaFuncSetAttribute((const void*)mma_mega, cudaFuncAttributeMaxDynamicSharedMemorySize, SMEM_BYTES);

#define SYM(p, s) do { void* _t; cudaGetSymbolAddress(&_t, s); p = (decltype(p))_t; } while (0)
    __half *Xhi, *Yhi, *Xkw_hi, *Xvw_hi, *Yqw_hi, *Yww_hi,
        *xk_hi, *yq_hi, *xvT_hi, *af_hi, *lattn, *o1p;
    SYM(Xhi, g_Xhi); SYM(Yhi, g_Yhi);
    SYM(Xkw_hi, g_Xkw_hi); SYM(Xvw_hi, g_Xvw_hi);
    SYM(Yqw_hi, g_Yqw_hi); SYM(Yww_hi, g_Yww_hi);
    SYM(xk_hi, g_xk_hi); SYM(yq_hi, g_yq_hi); SYM(xvT_hi, g_xvT_hi);
    SYM(af_hi, g_af_hi); SYM(lattn, g_lattn); SYM(o1p, g_o1);

    // ---- fused split (1 launch, compact flat grid) ----
    SplitArgs sa;
    sa.src[0] = X;    sa.hi[0] = Xhi;    sa.n4[0] = (long)XLEN * BSZ * XD / 4;
    sa.src[1] = Y;    sa.hi[1] = Yhi;    sa.n4[1] = (long)YLEN * BSZ * YD / 4;
    sa.src[2] = Xk_w; sa.hi[2] = Xkw_hi; sa.n4[2] = (long)HD * XD / 4;
    sa.src[3] = Xv_w; sa.hi[3] = Xvw_hi; sa.n4[3] = (long)HD * XD / 4;
    sa.src[4] = Yq_w; sa.hi[4] = Yqw_hi; sa.n4[4] = (long)HD * YD / 4;
    sa.src[5] = Yw_w; sa.hi[5] = Yww_hi; sa.n4[5] = (long)YOUT * CATD / 4;
    long off = 0;
    for (int i = 0; i < 6; i++) {
        sa.blk_off[i] = off;
        off += (sa.n4[i] + 255) / 256;
    }
    sa.blk_off[6] = off;
    split_all<<<(unsigned)off, 256>>>(sa);

    // ---- merged projections: xk, yq (striped) ----
    Gemm2 p2 = {};
    {
        GemmArgs a = {};
        a.Ah = Xhi; a.lda = XD; a.Abatch = 0;
        a.Bh = Xkw_hi; a.ldb = XD; a.Bbatch = 0;
        a.K = XD; a.Chi = xk_hi; a.ldc = HD; a.Cbatch = 0;
        a.bias = Xk_b; a.bias_rows = 0; a.scale = 1.0f;
        p2.a[0] = a;

        a.Ah = Yhi; a.lda = YD;
        a.Bh = Yqw_hi; a.ldb = YD;
        a.Chi = yq_hi; a.bias = Yq_b; a.scale = INV_SQRT_HD;
        p2.a[1] = a;
    }
    mma_gemm_proj<<<768, 256, SMEM_BYTES>>>(p2);

    // ---- mega: logits + xvT + out1 (striped 2048-block launch) ----
    Gemm3 p3 = {};
    {
        GemmArgs a = {};
        // logits: per batch M=1024(y) N=2048(x) K=512 -> fp16 in-place buffer
        a.Ah = yq_hi; a.lda = BSZ * HD; a.Abatch = HD;
        a.Bh = xk_hi; a.ldb = BSZ * HD; a.Bbatch = HD;
        a.K = HD; a.Chi = lattn; a.ldc = XLEN; a.Cbatch = (long)YLEN * XLEN;
        a.align = alignment; a.mask = mask; a.alignw = align_w; a.scale = 1.0f;
        p3.lg = a;

        // xvT[b,h,x] = Xv_w @ X[.,b,.]^T + Xv_b(row) : M=512(h) N=2048(x) K=1024
        a = {};
        a.Ah = Xvw_hi; a.lda = XD; a.Abatch = 0;
        a.Bh = Xhi; a.ldb = (long)BSZ * XD; a.Bbatch = XD;
        a.K = XD; a.Chi = xvT_hi; a.ldc = XLEN; a.Cbatch = (long)HD * XLEN;
        a.bias = Xv_b; a.bias_rows = 1; a.scale = 1.0f;
        p3.xv = a;

        // out1 = Y @ Yw[:, :YD]^T + bias : M=8192 N=1024 K=1024 -> fp16 o1
        a = {};
        a.Ah = Yhi; a.lda = YD; a.Abatch = 0;
        a.Bh = Yww_hi; a.ldb = CATD; a.Bbatch = 0;
        a.K = YD; a.Chi = o1p; a.ldc = YOUT; a.Cbatch = 0;
        a.bias = Yw_b; a.bias_rows = 0; a.scale = 1.0f;
        p3.o1 = a;
    }
    mma_mega<<<2048, 256, SMEM_BYTES>>>(p3);

    // ---- softmax (in place, fp16, fast-math) ----
    softmax_kernel<<<BSZ * YLEN, 256>>>();

    GemmArgs a = {};

    // ---- attn_feat = attn @ xvT^T -> af[(y,b),h] : per batch ----
    a.Ah = lattn; a.lda = XLEN; a.Abatch = (long)YLEN * XLEN;
    a.Bh = xvT_hi; a.ldb = XLEN; a.Bbatch = (long)HD * XLEN;
    a.K = XLEN; a.Chi = af_hi;
    a.ldc = (long)BSZ * HD; a.Cbatch = HD;
    a.bias = nullptr; a.bias_rows = 0; a.scale = 1.0f;
    mma_gemm<0><<<dim3(HD / 128, YLEN / 128, BSZ), 256, SMEM_BYTES>>>(a);

    // ---- out = o1 + af @ Yw[:, YD:]^T : M=8192 N=1024 K=512 ----
    a = {};
    a.Ah = af_hi; a.lda = HD; a.Abatch = 0;
    a.Bh = Yww_hi + YD; a.ldb = CATD; a.Bbatch = 0;
    a.K = HD; a.Cf = out; a.Cin16 = o1p; a.ldc = YOUT; a.Cbatch = 0;
    a.bias = nullptr; a.bias_rows = 0; a.scale = 1.0f;
    mma_gemm<4><<<dim3(YOUT / 128, YLEN * BSZ / 128, 1), 256, SMEM_BYTES>>>(a);
}

// round 17
// speedup vs baseline: 1.2410x; 1.0251x over previous
#include <cuda_runtime.h>
#include <cuda_fp16.h>
#include <math.h>
#include <stdint.h>

#define XLEN 2048
#define YLEN 1024
#define BSZ  8
#define XD   1024
#define YD   1024
#define HD   512
#define YOUT 1024
#define CATD (YD + HD)
#define FMAXV 3.402823466e38f
#define H16MAX 65504.0f
#define INV_SQRT_HD 0.04419417382415922f

// ===================== PTX helpers =====================
__device__ __forceinline__ uint32_t smem_u32(const void* p) {
    uint32_t a;
    asm("{ .reg .u64 t; cvta.to.shared.u64 t, %1; cvt.u32.u64 %0, t; }" : "=r"(a) : "l"(p));
    return a;
}
#define CP16(dst, src) \
    asm volatile("cp.async.cg.shared.global [%0], [%1], 16;" :: "r"(dst), "l"(src))
#define CP_COMMIT() asm volatile("cp.async.commit_group;")
#define PREF_L2(p) asm volatile("prefetch.global.L2 [%0];" :: "l"(p))

#define LDSM4(r, a) \
    asm volatile("ldmatrix.sync.aligned.m8n8.x4.shared.b16 {%0,%1,%2,%3}, [%4];" \
        : "=r"((r)[0]), "=r"((r)[1]), "=r"((r)[2]), "=r"((r)[3]) : "r"(a))

#define MMA_F16(d, a, b0v, b1v) \
    asm volatile("mma.sync.aligned.m16n8k16.row.col.f32.f16.f16.f32 " \
        "{%0,%1,%2,%3}, {%4,%5,%6,%7}, {%8,%9}, {%0,%1,%2,%3};" \
        : "+f"((d)[0]), "+f"((d)[1]), "+f"((d)[2]), "+f"((d)[3]) \
        : "r"((a)[0]), "r"((a)[1]), "r"((a)[2]), "r"((a)[3]), "r"(b0v), "r"(b1v))

// SMEM tile: 128 rows x 64 f16 (128B/row, 8 x 16B chunks), conflict-free swizzle.
__device__ __forceinline__ uint32_t swz64(int row, int ch) {
    return (uint32_t)(row * 128 + ((ch ^ (row & 7)) << 4));
}

// ===================== scratch (device globals) ==========================
#define AL __align__(16)
__device__ AL __half g_Xhi[XLEN * BSZ * XD];
__device__ AL __half g_Yhi[YLEN * BSZ * YD];
__device__ AL __half g_Xkw_hi[HD * XD];
__device__ AL __half g_Xvw_hi[HD * XD];
__device__ AL __half g_Yqw_hi[HD * YD];
__device__ AL __half g_Yww_hi[YOUT * CATD];
__device__ AL __half g_xk_hi[XLEN * BSZ * HD];
__device__ AL __half g_yq_hi[YLEN * BSZ * HD];
__device__ AL __half g_xvT_hi[BSZ * HD * XLEN];
__device__ AL __half g_af_hi[YLEN * BSZ * HD];
__device__ AL __half g_o1[YLEN * BSZ * YOUT];        // fp16 out1 staging
__device__ AL __half g_lattn[BSZ * YLEN * XLEN];     // fp16 exp(logits), unnormalized
__device__ AL float  g_rowsum[BSZ * YLEN];           // softmax denominators

// ===================== fused split: fp32 -> fp16 hi (compact grid) =======
struct SplitArgs {
    const float* src[6];
    __half* hi[6];
    long n4[6];
    long blk_off[7];
};

__global__ __launch_bounds__(256) void split_all(SplitArgs s)
{
    const long bid = blockIdx.x;
    int e = 0;
#pragma unroll
    for (int i = 1; i < 6; i++) if (bid >= s.blk_off[i]) e = i;
    long i4 = (bid - s.blk_off[e]) * 256 + threadIdx.x;
    if (i4 >= s.n4[e]) return;
    long base = i4 * 4;
    float4 v = *(const float4*)(s.src[e] + base);
    __half2 hp0 = {__float2half_rn(v.x), __float2half_rn(v.y)};
    __half2 hp1 = {__float2half_rn(v.z), __float2half_rn(v.w)};
    *(uint2*)(s.hi[e] + base) = make_uint2(*(uint32_t*)&hp0, *(uint32_t*)&hp1);
}

// ===================== fp16 GEMM core ====================================
// C[M,N] = Ah[M,K] @ Bh[N,K]^T
// Block 128x128, BK=64, 8 warps (2x4), warp tile 64x32, 3-stage cp.async,
// 2 CTAs/SM. Smem-staged coalesced epilogues.
// MODE 0: fp16 out (+bias col/row, scale).
// MODE 1: exp(v + sig*align) (0 if masked) -> fp16, + rowsum atomics.
// MODE 2: +bias -> fp32.  MODE 3: accumulate into fp32 C.
// MODE 4: v + fp16 Cin16 -> fp32 C.
// MODE 5: fp16 out, row-scaled by 1/rdiv[row].
struct GemmArgs {
    const __half *Ah, *Bh;
    long lda, ldb, Abatch, Bbatch;
    int K;
    float* Cf;
    __half *Chi;
    const __half* Cin16;
    long ldc, Cbatch;
    const float* bias;
    int bias_rows;
    float scale;
    const float* align;
    const int*   mask;
    const float* alignw;
    float* rowsum;          // MODE 1: accumulate; MODE 5: divide (rdiv)
    long rs_batch;
};

#define STG   32768            // Ah 16K | Bh 16K
#define NSTG  3
#define EPIT  136
#define SMEM_BYTES (NSTG * STG)

template <int MODE>
__device__ __forceinline__ void gemm_body(const GemmArgs& g, int bx, int by, int b)
{
    extern __shared__ char smem[];
    const uint32_t sb = smem_u32(smem);
    const int tid = threadIdx.x, wid = tid >> 5, lane = tid & 31;
    const long m0 = (long)by * 128, n0 = (long)bx * 128;
    const int wm = (wid >> 2) * 64;
    const int wn = (wid & 3) * 32;

    const __half* Ah = g.Ah + (long)b * g.Abatch;
    const __half* Bh = g.Bh + (long)b * g.Bbatch;

    const int lrow = tid >> 3, lch = tid & 7;
    const uint32_t sw0 = swz64(lrow, lch);
    const long ga0 = (m0 + lrow) * g.lda + lch * 8;
    const long gb0 = (n0 + lrow) * g.ldb + lch * 8;
    const long astep = 32 * g.lda, bstep = 32 * g.ldb;

    const int NT = g.K >> 6;
    const int a_r = lane & 15, a_c = lane >> 4;
    const int b_r = (lane & 7) + ((lane >> 4) & 1) * 8, b_c = (lane >> 3) & 1;

    float acc[4][4][4];
#pragma unroll
    for (int i = 0; i < 4; i++)
#pragma unroll
        for (int j = 0; j < 4; j++)
#pragma unroll
            for (int k = 0; k < 4; k++) acc[i][j][k] = 0.0f;

    auto load_stage = [&](int s, int it) {
        const long k0 = (long)it << 6;
        const uint32_t base = sb + s * STG;
#pragma unroll
        for (int i = 0; i < 4; i++) {
            CP16(base + sw0 + i * 4096,         (const char*)(Ah + ga0 + i * astep + k0));
            CP16(base + 16384 + sw0 + i * 4096, (const char*)(Bh + gb0 + i * bstep + k0));
        }
        CP_COMMIT();
    };

    load_stage(0, 0);
    load_stage(1, 1);

    // warm L2 with the epilogue's gmem inputs while the mainloop runs
    if (MODE == 1) {
#pragma unroll
        for (int i = 0; i < 2; i++) {
            const int gid = tid + i * 256;
            const int row = gid >> 2, seg = gid & 3;
            const long idx = (long)b * g.Cbatch + (m0 + row) * g.ldc + n0 + seg * 32;
            PREF_L2(g.align + idx);
            PREF_L2(g.mask + idx);
        }
    } else if (MODE == 4) {
        const int row = tid >> 1, seg = tid & 1;
        const long idx = (long)b * g.Cbatch + (m0 + row) * g.ldc + n0 + seg * 64;
        PREF_L2(g.Cin16 + idx);
    }

    int cur = 0, nxt = 2;
    for (int it = 0; it < NT; ++it) {
        asm volatile("cp.async.wait_group 1;");
        __syncthreads();
        if (it + 2 < NT) {
            load_stage(nxt, it + 2);
            if (++nxt == NSTG) nxt = 0;
        } else CP_COMMIT();

        const uint32_t st = sb + cur * STG;
        if (++cur == NSTG) cur = 0;
#pragma unroll
        for (int ks = 0; ks < 4; ks++) {
            const int kc = ks * 2;
            uint32_t ah[4][4], bh[2][4];
#pragma unroll
            for (int mi = 0; mi < 4; mi++)
                LDSM4(ah[mi], st + swz64(wm + mi * 16 + a_r, kc + a_c));
#pragma unroll
            for (int nb = 0; nb < 2; nb++)
                LDSM4(bh[nb], st + 16384 + swz64(wn + nb * 16 + b_r, kc + b_c));
#pragma unroll
            for (int mi = 0; mi < 4; mi++)
#pragma unroll
                for (int ni = 0; ni < 4; ni++) {
                    const int nb = ni >> 1, sub = (ni & 1) * 2;
                    MMA_F16(acc[mi][ni], ah[mi], bh[nb][sub], bh[nb][sub + 1]);
                }
        }
    }
    __syncthreads();   // pipeline smem now reusable as staging

    // ---- stage acc tile to smem ----
    float* sf = (float*)smem;
#pragma unroll
    for (int mi = 0; mi < 4; mi++)
#pragma unroll
        for (int ni = 0; ni < 4; ni++) {
            const int row = wm + mi * 16 + (lane >> 2);
            const int col = wn + ni * 8 + (lane & 3) * 2;
            *(float2*)&sf[row * EPIT + col] =
                make_float2(acc[mi][ni][0], acc[mi][ni][1]);
            *(float2*)&sf[(row + 8) * EPIT + col] =
                make_float2(acc[mi][ni][2], acc[mi][ni][3]);
        }
    __syncthreads();

    // ---- thread-linear gmem phase: coalesced 16B transactions ----
    if (MODE == 0 || MODE == 5) {
        const float sc = g.scale;
        const float* rs = (MODE == 5) ? g.rowsum + (long)b * g.rs_batch + m0 : nullptr;
#pragma unroll
        for (int i = 0; i < 8; i++) {
            const int gid = tid + i * 256;
            const int row = gid >> 4, c0 = (gid & 15) * 8;
            float4 va = *(float4*)&sf[row * EPIT + c0];
            float4 vb = *(float4*)&sf[row * EPIT + c0 + 4];
            float v[8] = {va.x, va.y, va.z, va.w, vb.x, vb.y, vb.z, vb.w};
            if (MODE == 0 && g.bias) {
                if (g.bias_rows) {
                    const float br = __ldg(&g.bias[m0 + row]);
#pragma unroll
                    for (int j = 0; j < 8; j++) v[j] += br;
                } else {
                    float4 b0 = *(const float4*)&g.bias[n0 + c0];
                    float4 b1 = *(const float4*)&g.bias[n0 + c0 + 4];
                    v[0] += b0.x; v[1] += b0.y; v[2] += b0.z; v[3] += b0.w;
                    v[4] += b1.x; v[5] += b1.y; v[6] += b1.z; v[7] += b1.w;
                }
            }
            float mul = sc;
            if (MODE == 5) mul = __fdividef(1.0f, __ldg(rs + row));
            uint4 u;
            __half2 h0 = {__float2half_rn(v[0] * mul), __float2half_rn(v[1] * mul)};
            __half2 h1 = {__float2half_rn(v[2] * mul), __float2half_rn(v[3] * mul)};
            __half2 h2 = {__float2half_rn(v[4] * mul), __float2half_rn(v[5] * mul)};
            __half2 h3 = {__float2half_rn(v[6] * mul), __float2half_rn(v[7] * mul)};
            u.x = *(uint32_t*)&h0; u.y = *(uint32_t*)&h1;
            u.z = *(uint32_t*)&h2; u.w = *(uint32_t*)&h3;
            const long idx = (long)b * g.Cbatch + (m0 + row) * g.ldc + n0 + c0;
            *(uint4*)(g.Chi + idx) = u;
        }
    } else if (MODE == 1) {
        const float sig = 1.0f / (1.0f + __expf(-__ldg(g.alignw)));
        float* rs = g.rowsum + (long)b * g.rs_batch + m0;
#pragma unroll
        for (int i = 0; i < 8; i++) {
            const int gid = tid + i * 256;
            const int row = gid >> 4, c0 = (gid & 15) * 8;
            float4 va = *(float4*)&sf[row * EPIT + c0];
            float4 vb = *(float4*)&sf[row * EPIT + c0 + 4];
            float v[8] = {va.x, va.y, va.z, va.w, vb.x, vb.y, vb.z, vb.w};
            const long idx = (long)b * g.Cbatch + (m0 + row) * g.ldc + n0 + c0;
            float4 a0 = *(const float4*)(g.align + idx);
            float4 a1 = *(const float4*)(g.align + idx + 4);
            int4   m0v = *(const int4*)(g.mask + idx);
            int4   m1v = *(const int4*)(g.mask + idx + 4);
            float av[8] = {a0.x, a0.y, a0.z, a0.w, a1.x, a1.y, a1.z, a1.w};
            int   mv[8] = {m0v.x, m0v.y, m0v.z, m0v.w, m1v.x, m1v.y, m1v.z, m1v.w};
            __half2 hh[4];
            float lsum = 0.0f;
#pragma unroll
            for (int j = 0; j < 8; j++) {
                float e = (mv[j] != 0) ? 0.0f : __expf(v[j] + sig * av[j]);
                lsum += e;
                if ((j & 1) == 0) hh[j >> 1].x = __float2half_rn(e);
                else              hh[j >> 1].y = __float2half_rn(e);
            }
            uint4 u;
            u.x = *(uint32_t*)&hh[0]; u.y = *(uint32_t*)&hh[1];
            u.z = *(uint32_t*)&hh[2]; u.w = *(uint32_t*)&hh[3];
            *(uint4*)(g.Chi + idx) = u;
            // reduce within the 16-lane half owning this row, then atomic
            lsum += __shfl_xor_sync(0xffffffff, lsum, 1);
            lsum += __shfl_xor_sync(0xffffffff, lsum, 2);
            lsum += __shfl_xor_sync(0xffffffff, lsum, 4);
            lsum += __shfl_xor_sync(0xffffffff, lsum, 8);
            if ((lane & 15) == 0) atomicAdd(rs + row, lsum);
        }
    } else if (MODE == 2) {
#pragma unroll
        for (int i = 0; i < 16; i++) {
            const int gid = tid + i * 256;
            const int row = gid >> 5, c0 = (gid & 31) * 4;
            float4 v = *(float4*)&sf[row * EPIT + c0];
            float4 b4 = *(const float4*)&g.bias[n0 + c0];
            const long idx = (long)b * g.Cbatch + (m0 + row) * g.ldc + n0 + c0;
            *(float4*)(g.Cf + idx) =
                make_float4(v.x + b4.x, v.y + b4.y, v.z + b4.z, v.w + b4.w);
        }
    } else if (MODE == 3) {
#pragma unroll
        for (int i = 0; i < 16; i++) {
            const int gid = tid + i * 256;
            const int row = gid >> 5, c0 = (gid & 31) * 4;
            float4 v = *(float4*)&sf[row * EPIT + c0];
            const long idx = (long)b * g.Cbatch + (m0 + row) * g.ldc + n0 + c0;
            float4 o = *(float4*)(g.Cf + idx);
            *(float4*)(g.Cf + idx) =
                make_float4(v.x + o.x, v.y + o.y, v.z + o.z, v.w + o.w);
        }
    } else {  // MODE 4: v + fp16 Cin16 -> fp32
#pragma unroll
        for (int i = 0; i < 8; i++) {
            const int gid = tid + i * 256;
            const int row = gid >> 4, c0 = (gid & 15) * 8;
            float4 va = *(float4*)&sf[row * EPIT + c0];
            float4 vb = *(float4*)&sf[row * EPIT + c0 + 4];
            const long idx = (long)b * g.Cbatch + (m0 + row) * g.ldc + n0 + c0;
            uint4 hv = *(const uint4*)(g.Cin16 + idx);
            __half2* hh = (__half2*)&hv;
            float2 f0 = __half22float2(hh[0]);
            float2 f1 = __half22float2(hh[1]);
            float2 f2 = __half22float2(hh[2]);
            float2 f3 = __half22float2(hh[3]);
            *(float4*)(g.Cf + idx) =
                make_float4(va.x + f0.x, va.y + f0.y, va.z + f1.x, va.w + f1.y);
            *(float4*)(g.Cf + idx + 4) =
                make_float4(vb.x + f2.x, vb.y + f2.y, vb.z + f3.x, vb.w + f3.y);
        }
    }
}

template <int MODE>
__global__ __launch_bounds__(256, 2) void mma_gemm(GemmArgs g)
{
    gemm_body<MODE>(g, blockIdx.x, blockIdx.y, blockIdx.z);
}

// merged projections (xk, yq), striped 2:1 so waves mix both
struct Gemm2 { GemmArgs a[2]; };
__global__ __launch_bounds__(256, 2) void mma_gemm_proj(Gemm2 p)
{
    const int id = blockIdx.x;         // 768 = 256 groups x {xk, xk, yq}
    const int grp = id / 3, r = id - grp * 3;
    if (r < 2) {
        const int t = grp * 2 + r;     // 0..511 : xk
        gemm_body<0>(p.a[0], t & 3, t >> 2, 0);
    } else {
        const int t = grp;             // 0..255 : yq
        gemm_body<0>(p.a[1], t & 3, t >> 2, 0);
    }
}

// mega: logits(1024) | xvT(512) | out1(512), striped {lg,lg,xv,o1} per 4 ids
struct Gemm3 { GemmArgs lg, xv, o1; };
__global__ __launch_bounds__(256, 2) void mma_mega(Gemm3 p)
{
    const int id = blockIdx.x;
    const int grp = id >> 2, r = id & 3;
    if (r < 2) {
        const int t = grp * 2 + r;     // 0..1023 : logits (16 x 8 x 8)
        gemm_body<1>(p.lg, t & 15, (t >> 4) & 7, t >> 7);
    } else if (r == 2) {
        const int t = grp;             // 0..511 : xvT — by fastest for L2 reuse
        gemm_body<0>(p.xv, (t >> 2) & 15, t & 3, t >> 6);
    } else {
        const int t = grp;             // 0..511 : out1 -> fp16 o1
        gemm_body<0>(p.o1, t & 7, t >> 3, 0);
    }
}

// ===================== launch ============================================
extern "C" void kernel_launch(void* const* d_in, const int* in_sizes, int n_in,
                              void* d_out, int out_size)
{
    const float* X         = (const float*)d_in[0];
    const float* Y         = (const float*)d_in[1];
    const float* alignment = (const float*)d_in[2];
    const int*   mask      = (const int*)d_in[3];
    const float* Xk_w      = (const float*)d_in[4];
    const float* Xk_b      = (const float*)d_in[5];
    const float* Xv_w      = (const float*)d_in[6];
    const float* Xv_b      = (const float*)d_in[7];
    const float* Yq_w      = (const float*)d_in[8];
    const float* Yq_b      = (const float*)d_in[9];
    const float* Yw_w      = (const float*)d_in[10];
    const float* Yw_b      = (const float*)d_in[11];
    const float* align_w   = (const float*)d_in[12];
    float* out = (float*)d_out;

    cudaFuncSetAttribute((const void*)mma_gemm<5>, cudaFuncAttributeMaxDynamicSharedMemorySize, SMEM_BYTES);
    cudaFuncSetAttribute((const void*)mma_gemm<4>, cudaFuncAttributeMaxDynamicSharedMemorySize, SMEM_BYTES);
    cudaFuncSetAttribute((const void*)mma_gemm_proj, cudaFuncAttributeMaxDynamicSharedMemorySize, SMEM_BYTES);
    cudaFuncSetAttribute((const void*)mma_mega, cudaFuncAttributeMaxDynamicSharedMemorySize, SMEM_BYTES);

#define SYM(p, s) do { void* _t; cudaGetSymbolAddress(&_t, s); p = (decltype(p))_t; } while (0)
    __half *Xhi, *Yhi, *Xkw_hi, *Xvw_hi, *Yqw_hi, *Yww_hi,
        *xk_hi, *yq_hi, *xvT_hi, *af_hi, *lattn, *o1p;
    float* rowsum;
    SYM(Xhi, g_Xhi); SYM(Yhi, g_Yhi);
    SYM(Xkw_hi, g_Xkw_hi); SYM(Xvw_hi, g_Xvw_hi);
    SYM(Yqw_hi, g_Yqw_hi); SYM(Yww_hi, g_Yww_hi);
    SYM(xk_hi, g_xk_hi); SYM(yq_hi, g_yq_hi); SYM(xvT_hi, g_xvT_hi);
    SYM(af_hi, g_af_hi); SYM(lattn, g_lattn); SYM(o1p, g_o1);
    SYM(rowsum, g_rowsum);

    // ---- fused split (1 launch, compact flat grid) ----
    SplitArgs sa;
    sa.src[0] = X;    sa.hi[0] = Xhi;    sa.n4[0] = (long)XLEN * BSZ * XD / 4;
    sa.src[1] = Y;    sa.hi[1] = Yhi;    sa.n4[1] = (long)YLEN * BSZ * YD / 4;
    sa.src[2] = Xk_w; sa.hi[2] = Xkw_hi; sa.n4[2] = (long)HD * XD / 4;
    sa.src[3] = Xv_w; sa.hi[3] = Xvw_hi; sa.n4[3] = (long)HD * XD / 4;
    sa.src[4] = Yq_w; sa.hi[4] = Yqw_hi; sa.n4[4] = (long)HD * YD / 4;
    sa.src[5] = Yw_w; sa.hi[5] = Yww_hi; sa.n4[5] = (long)YOUT * CATD / 4;
    long off = 0;
    for (int i = 0; i < 6; i++) {
        sa.blk_off[i] = off;
        off += (sa.n4[i] + 255) / 256;
    }
    sa.blk_off[6] = off;
    split_all<<<(unsigned)off, 256>>>(sa);

    // zero rowsum (graph-capturable async memset)
    cudaMemsetAsync(rowsum, 0, BSZ * YLEN * sizeof(float));

    // ---- merged projections: xk, yq (striped) ----
    Gemm2 p2 = {};
    {
        GemmArgs a = {};
        a.Ah = Xhi; a.lda = XD; a.Abatch = 0;
        a.Bh = Xkw_hi; a.ldb = XD; a.Bbatch = 0;
        a.K = XD; a.Chi = xk_hi; a.ldc = HD; a.Cbatch = 0;
        a.bias = Xk_b; a.bias_rows = 0; a.scale = 1.0f;
        p2.a[0] = a;

        a.Ah = Yhi; a.lda = YD;
        a.Bh = Yqw_hi; a.ldb = YD;
        a.Chi = yq_hi; a.bias = Yq_b; a.scale = INV_SQRT_HD;
        p2.a[1] = a;
    }
    mma_gemm_proj<<<768, 256, SMEM_BYTES>>>(p2);

    // ---- mega: logits(+exp+rowsum) + xvT + out1 ----
    Gemm3 p3 = {};
    {
        GemmArgs a = {};
        a.Ah = yq_hi; a.lda = BSZ * HD; a.Abatch = HD;
        a.Bh = xk_hi; a.ldb = BSZ * HD; a.Bbatch = HD;
        a.K = HD; a.Chi = lattn; a.ldc = XLEN; a.Cbatch = (long)YLEN * XLEN;
        a.align = alignment; a.mask = mask; a.alignw = align_w; a.scale = 1.0f;
        a.rowsum = rowsum; a.rs_batch = YLEN;
        p3.lg = a;

        a = {};
        a.Ah = Xvw_hi; a.lda = XD; a.Abatch = 0;
        a.Bh = Xhi; a.ldb = (long)BSZ * XD; a.Bbatch = XD;
        a.K = XD; a.Chi = xvT_hi; a.ldc = XLEN; a.Cbatch = (long)HD * XLEN;
        a.bias = Xv_b; a.bias_rows = 1; a.scale = 1.0f;
        p3.xv = a;

        a = {};
        a.Ah = Yhi; a.lda = YD; a.Abatch = 0;
        a.Bh = Yww_hi; a.ldb = CATD; a.Bbatch = 0;
        a.K = YD; a.Chi = o1p; a.ldc = YOUT; a.Cbatch = 0;
        a.bias = Yw_b; a.bias_rows = 0; a.scale = 1.0f;
        p3.o1 = a;
    }
    mma_mega<<<2048, 256, SMEM_BYTES>>>(p3);

    GemmArgs a = {};

    // ---- af = (exp_attn @ xvT^T) / rowsum -> af[(y,b),h] : per batch ----
    a.Ah = lattn; a.lda = XLEN; a.Abatch = (long)YLEN * XLEN;
    a.Bh = xvT_hi; a.ldb = XLEN; a.Bbatch = (long)HD * XLEN;
    a.K = XLEN; a.Chi = af_hi;
    a.ldc = (long)BSZ * HD; a.Cbatch = HD;
    a.bias = nullptr; a.bias_rows = 0; a.scale = 1.0f;
    a.rowsum = rowsum; a.rs_batch = YLEN;
    mma_gemm<5><<<dim3(HD / 128, YLEN / 128, BSZ), 256, SMEM_BYTES>>>(a);

    // ---- out = o1 + af @ Yw[:, YD:]^T : M=8192 N=1024 K=512 ----
    a = {};
    a.Ah = af_hi; a.lda = HD; a.Abatch = 0;
    a.Bh = Yww_hi + YD; a.ldb = CATD; a.Bbatch = 0;
    a.K = HD; a.Cf = out; a.Cin16 = o1p; a.ldc = YOUT; a.Cbatch = 0;
    a.bias = nullptr; a.bias_rows = 0; a.scale = 1.0f;
    mma_gemm<4><<<dim3(YOUT / 128, YLEN * BSZ / 128, 1), 256, SMEM_BYTES>>>(a);
}